// round 6
// baseline (speedup 1.0000x reference)
#include <cuda_runtime.h>
#include <cuda_bf16.h>
#include <math_constants.h>
#include <cstdint>

// Problem constants
#define BQ   4
#define LQ   4096
#define DQ   128
#define NBQ  64
#define MTOT (BQ * LQ)     // 16384 rows
#define NPAIR (NBQ / 2)    // 32 qblock pairs

// ---------------------------------------------------------------------------
// Scratch (__device__ globals; no allocations allowed)
// ---------------------------------------------------------------------------
__device__ __nv_bfloat16 g_Xh[6 * MTOT * DQ];       // input hi/lo split (plane-major)
__device__ __nv_bfloat16 g_Xl[6 * MTOT * DQ];
__device__ __nv_bfloat16 g_Wqh[768 * 768];
__device__ __nv_bfloat16 g_Wql[768 * 768];
__device__ __nv_bfloat16 g_QKVh[6 * MTOT * DQ];     // QKV projection out, hi/lo
__device__ __nv_bfloat16 g_QKVl[6 * MTOT * DQ];
__device__ __nv_bfloat16 g_Ath[MTOT * 256];         // attention out, hi/lo
__device__ __nv_bfloat16 g_Atl[MTOT * 256];
__device__ __nv_bfloat16 g_Woh[256 * 256];
__device__ __nv_bfloat16 g_Wol[256 * 256];
__device__ int g_ucnt[NPAIR];
__device__ int g_ulist[NPAIR][2 * NBQ];
__device__ int g_uflg[NPAIR][2 * NBQ];

// ---------------------------------------------------------------------------
// Helpers
// ---------------------------------------------------------------------------
__device__ __forceinline__ uint32_t smem_to_u32(const void* p) {
    uint32_t a;
    asm("{ .reg .u64 t; cvta.to.shared.u64 t, %1; cvt.u32.u64 %0, t; }" : "=r"(a) : "l"(p));
    return a;
}
__device__ __forceinline__ void cp16(uint32_t dst_smem, const void* src) {
    asm volatile("cp.async.cg.shared.global [%0], [%1], 16;" :: "r"(dst_smem), "l"(src));
}
#define CP_COMMIT() asm volatile("cp.async.commit_group;" ::: "memory")
#define CP_WAIT(n)  asm volatile("cp.async.wait_group %0;" :: "n"(n) : "memory")

__device__ __forceinline__ void ldmx4(uint32_t* r, uint32_t addr) {
    asm volatile("ldmatrix.sync.aligned.m8n8.x4.shared.b16 {%0,%1,%2,%3}, [%4];"
                 : "=r"(r[0]), "=r"(r[1]), "=r"(r[2]), "=r"(r[3]) : "r"(addr));
}
__device__ __forceinline__ void ldmx4t(uint32_t* r, uint32_t addr) {
    asm volatile("ldmatrix.sync.aligned.m8n8.x4.trans.shared.b16 {%0,%1,%2,%3}, [%4];"
                 : "=r"(r[0]), "=r"(r[1]), "=r"(r[2]), "=r"(r[3]) : "r"(addr));
}
__device__ __forceinline__ void ldmx2(uint32_t* r, uint32_t addr) {
    asm volatile("ldmatrix.sync.aligned.m8n8.x2.shared.b16 {%0,%1}, [%2];"
                 : "=r"(r[0]), "=r"(r[1]) : "r"(addr));
}
__device__ __forceinline__ void mma_bf16(float* c, const uint32_t* a,
                                         uint32_t b0, uint32_t b1) {
    asm volatile(
        "mma.sync.aligned.m16n8k16.row.col.f32.bf16.bf16.f32 "
        "{%0,%1,%2,%3}, {%4,%5,%6,%7}, {%8,%9}, {%0,%1,%2,%3};"
        : "+f"(c[0]), "+f"(c[1]), "+f"(c[2]), "+f"(c[3])
        : "r"(a[0]), "r"(a[1]), "r"(a[2]), "r"(a[3]), "r"(b0), "r"(b1));
}
__device__ __forceinline__ uint32_t pack_bf2(float a, float b) {
    __nv_bfloat162 t = __floats2bfloat162_rn(a, b);
    return *(uint32_t*)&t;
}
__device__ __forceinline__ void split2(float a, float b, uint32_t& h, uint32_t& l) {
    __nv_bfloat16 ha = __float2bfloat16(a);
    __nv_bfloat16 hb = __float2bfloat16(b);
    h = ((uint32_t)__bfloat16_as_ushort(hb) << 16) | __bfloat16_as_ushort(ha);
    l = pack_bf2(a - __bfloat162float(ha), b - __bfloat162float(hb));
}

// ---------------------------------------------------------------------------
// Block-mask compaction: per qblock-PAIR union lists + participation flags
// ---------------------------------------------------------------------------
__global__ void build_mask_kernel(const void* __restrict__ mask)
{
    int p = threadIdx.x;
    if (p >= NPAIR) return;
    const float* mf = (const float*)mask;
    const int*   mi = (const int*)mask;
    const unsigned char* mb = (const unsigned char*)mask;
    int mode;
    if (mf[0] == 1.0f)   mode = 0;
    else if (mi[0] == 1) mode = 1;
    else                 mode = 2;

    auto test = [&](int qb, int kb) -> bool {
        size_t idx = (size_t)(qb * 64) * (size_t)LQ + (size_t)(kb * 64);
        if (mode == 0) return mf[idx] != 0.0f;
        if (mode == 1) return mi[idx] != 0;
        return mb[idx] != 0;
    };

    int qb0 = 2 * p, qb1 = 2 * p + 1;
    int cnt = 0;
    for (int kb = 0; kb <= qb1; kb++) {
        bool on0 = (kb <= qb0) && test(qb0, kb);
        bool on1 = test(qb1, kb);
        if (on0 || on1) {
            g_ulist[p][cnt] = kb;
            g_uflg[p][cnt]  = (on0 ? 1 : 0) | (on1 ? 2 : 0);
            cnt++;
        }
    }
    g_ucnt[p] = cnt;
}

// ---------------------------------------------------------------------------
// fp32 -> bf16 hi/lo split: all 6 input planes in one launch (grid.y=plane)
// ---------------------------------------------------------------------------
#define PLANE4 (MTOT * DQ / 4)
__global__ void split6_kernel(
    const float4* __restrict__ s0, const float4* __restrict__ s1,
    const float4* __restrict__ s2, const float4* __restrict__ s3,
    const float4* __restrict__ s4, const float4* __restrict__ s5,
    uint2* __restrict__ hi, uint2* __restrict__ lo)
{
    int plane = blockIdx.y;
    const float4* src = (plane == 0) ? s0 : (plane == 1) ? s1 : (plane == 2) ? s2
                      : (plane == 3) ? s3 : (plane == 4) ? s4 : s5;
    int i = blockIdx.x * 256 + threadIdx.x;     // PLANE4 = 524288 exact multiple
    float4 v = src[i];
    float f[4] = {v.x, v.y, v.z, v.w};
    uint32_t hw[4], lw[4];
#pragma unroll
    for (int j = 0; j < 4; j++) {
        __nv_bfloat16 h = __float2bfloat16(f[j]);
        __nv_bfloat16 l = __float2bfloat16(f[j] - __bfloat162float(h));
        hw[j] = (uint32_t)__bfloat16_as_ushort(h);
        lw[j] = (uint32_t)__bfloat16_as_ushort(l);
    }
    size_t o = (size_t)plane * PLANE4 + i;
    hi[o] = make_uint2((hw[1] << 16) | hw[0], (hw[3] << 16) | hw[2]);
    lo[o] = make_uint2((lw[1] << 16) | lw[0], (lw[3] << 16) | lw[2]);
}

// single-tensor split (for the two weight matrices)
__global__ void split_kernel(const float4* __restrict__ src,
                             uint2* __restrict__ hi, uint2* __restrict__ lo, int n4)
{
    int i = blockIdx.x * 256 + threadIdx.x;
    if (i >= n4) return;
    float4 v = src[i];
    float f[4] = {v.x, v.y, v.z, v.w};
    uint32_t hw[4], lw[4];
#pragma unroll
    for (int j = 0; j < 4; j++) {
        __nv_bfloat16 h = __float2bfloat16(f[j]);
        __nv_bfloat16 l = __float2bfloat16(f[j] - __bfloat162float(h));
        hw[j] = (uint32_t)__bfloat16_as_ushort(h);
        lw[j] = (uint32_t)__bfloat16_as_ushort(l);
    }
    hi[i] = make_uint2((hw[1] << 16) | hw[0], (hw[3] << 16) | hw[2]);
    lo[i] = make_uint2((lw[1] << 16) | lw[0], (lw[3] << 16) | lw[2]);
}

// ---------------------------------------------------------------------------
// HMMA GEMM (3-term bf16 hi/lo split). Tile 128x128x32, 8 warps.
// MODE 0: QKV (K=768) -> writes bf16 hi/lo planes g_QKVh/g_QKVl
// MODE 1: OUT (K=256) -> writes fp32 halves of d_out
// ---------------------------------------------------------------------------
#define GSTRIDE 40
#define MATE    (128 * GSTRIDE)
#define MATB    (MATE * 2)
#define STAGEB  (4 * MATB)
#define GEMM_SMEM (2 * STAGEB)

template<int MODE>
__global__ __launch_bounds__(256, 1) void gemm_mma_impl(
    const __nv_bfloat16* __restrict__ Ah, const __nv_bfloat16* __restrict__ Al,
    const __nv_bfloat16* __restrict__ Bh, const __nv_bfloat16* __restrict__ Bl,
    const float* __restrict__ bias, float* __restrict__ Cout)
{
    constexpr int KTOT = (MODE == 0) ? 768 : 256;
    constexpr int NCH  = KTOT / 32;

    extern __shared__ __align__(128) char smc[];
    uint32_t sbase0 = smem_to_u32(smc);

    int tid  = threadIdx.x;
    int warp = tid >> 5, lane = tid & 31;
    int wm = warp & 1;
    int wn = warp >> 1;
    int m0 = blockIdx.y * 128;
    int n0 = blockIdx.x * 128;

    auto load_stage = [&](int ch, int buf) {
        int k0 = ch * 32;
        uint32_t sb = sbase0 + buf * STAGEB;
#pragma unroll
        for (int i = 0; i < 2; i++) {
            int e = tid + i * 256;
            int r = e >> 2, seg = e & 3;
            uint32_t off = (uint32_t)(r * GSTRIDE + seg * 8) * 2;
            size_t ga;
            if (MODE == 0) ga = ((size_t)(k0 >> 7) * MTOT + m0 + r) * 128 + (k0 & 127) + seg * 8;
            else           ga = (size_t)(m0 + r) * KTOT + k0 + seg * 8;
            cp16(sb + off,            Ah + ga);
            cp16(sb + MATB + off,     Al + ga);
            size_t gb = (size_t)(n0 + r) * KTOT + k0 + seg * 8;
            cp16(sb + 2 * MATB + off, Bh + gb);
            cp16(sb + 3 * MATB + off, Bl + gb);
        }
    };

    float acc[4][4][4];
#pragma unroll
    for (int mf = 0; mf < 4; mf++)
#pragma unroll
        for (int nf = 0; nf < 4; nf++)
#pragma unroll
            for (int j = 0; j < 4; j++) acc[mf][nf][j] = 0.f;

    load_stage(0, 0); CP_COMMIT();
    load_stage(1, 1); CP_COMMIT();
    CP_WAIT(1);
    __syncthreads();

    int li = lane & 15;
    uint32_t a_row_off = (uint32_t)((wm * 64 + li) * GSTRIDE) * 2;
    uint32_t a_col_off = (uint32_t)((lane >> 4) * 8) * 2;
    uint32_t b_row_off = (uint32_t)((wn * 32 + (li & 7)) * GSTRIDE) * 2;
    uint32_t b_col_off = (uint32_t)((li >> 3) * 8) * 2;

    for (int ch = 0; ch < NCH; ch++) {
        uint32_t sb = sbase0 + (ch & 1) * STAGEB;
#pragma unroll
        for (int k16 = 0; k16 < 2; k16++) {
            uint32_t kofs = (uint32_t)(k16 * 16) * 2;
            uint32_t ah[4][4], al[4][4];
#pragma unroll
            for (int mf = 0; mf < 4; mf++) {
                uint32_t addr = sb + a_row_off
                              + (uint32_t)(mf * 16 * GSTRIDE * 2) + kofs + a_col_off;
                ldmx4(ah[mf], addr);
                ldmx4(al[mf], addr + MATB);
            }
            uint32_t bh[4][2], bl[4][2];
#pragma unroll
            for (int nf = 0; nf < 4; nf++) {
                uint32_t addr = sb + 2 * MATB + b_row_off
                              + (uint32_t)(nf * 8 * GSTRIDE * 2) + kofs + b_col_off;
                ldmx2(bh[nf], addr);
                ldmx2(bl[nf], addr + MATB);
            }
#pragma unroll
            for (int mf = 0; mf < 4; mf++)
#pragma unroll
                for (int nf = 0; nf < 4; nf++) {
                    mma_bf16(acc[mf][nf], ah[mf], bh[nf][0], bh[nf][1]);
                    mma_bf16(acc[mf][nf], ah[mf], bl[nf][0], bl[nf][1]);
                    mma_bf16(acc[mf][nf], al[mf], bh[nf][0], bh[nf][1]);
                }
        }
        __syncthreads();
        if (ch + 2 < NCH) { load_stage(ch + 2, ch & 1); CP_COMMIT(); }
        if (ch + 1 < NCH) {
            if (ch + 2 < NCH) { CP_WAIT(1); } else { CP_WAIT(0); }
            __syncthreads();
        }
    }

    // epilogue
#pragma unroll
    for (int mf = 0; mf < 4; mf++) {
        int r0 = m0 + wm * 64 + mf * 16 + (lane >> 2);
#pragma unroll
        for (int nf = 0; nf < 4; nf++) {
            int cp = wn * 32 + nf * 8 + (lane & 3) * 2;
            float b0 = __ldg(bias + blockIdx.x * 128 + cp);
            float b1 = __ldg(bias + blockIdx.x * 128 + cp + 1);
            float v00 = acc[mf][nf][0] + b0, v01 = acc[mf][nf][1] + b1;
            float v10 = acc[mf][nf][2] + b0, v11 = acc[mf][nf][3] + b1;
            if (MODE == 0) {
                size_t base = (size_t)blockIdx.x * MTOT * 128;
                uint32_t w0h, w0l, w1h, w1l;
                split2(v00, v01, w0h, w0l);
                split2(v10, v11, w1h, w1l);
                *(uint32_t*)(g_QKVh + base + (size_t)r0 * 128 + cp)       = w0h;
                *(uint32_t*)(g_QKVl + base + (size_t)r0 * 128 + cp)       = w0l;
                *(uint32_t*)(g_QKVh + base + (size_t)(r0 + 8) * 128 + cp) = w1h;
                *(uint32_t*)(g_QKVl + base + (size_t)(r0 + 8) * 128 + cp) = w1l;
            } else {
                float* dst = Cout + (size_t)blockIdx.x * MTOT * 128;
                *(float2*)(dst + (size_t)r0 * 128 + cp)       = make_float2(v00, v01);
                *(float2*)(dst + (size_t)(r0 + 8) * 128 + cp) = make_float2(v10, v11);
            }
        }
    }
}

// ---------------------------------------------------------------------------
// HMMA block-sparse flash attention, 128-query CTAs.
// Grid (NPAIR, 2, BQ); 256 threads = 8 warps. Warp-group g = warp>>2 handles
// qblock 2*blockIdx.x+g; per-pair union k-block list with participation flags.
// S and PV are 3-term bf16 hi/lo. K/V double-buffered cp.async.
// Epilogue writes bf16 hi/lo directly (feeds out-projection GEMM).
// ---------------------------------------------------------------------------
#define AST   136
#define AMATB (64 * AST * 2)            // 17408 bytes per 64x128 matrix
#define QMATB (128 * AST * 2)           // 34816 bytes per 128x128 matrix
#define ATT_SMEM (2 * QMATB + 8 * AMATB)  // 208896 bytes

__global__ __launch_bounds__(256, 1) void attn_mma()
{
    extern __shared__ __align__(128) char sma[];
    uint32_t sb = smem_to_u32(sma);

    int tid  = threadIdx.x;
    int warp = tid >> 5, lane = tid & 31;
    int grp  = warp >> 2;              // 0/1 -> qblock within pair
    int pair = blockIdx.x;
    int part = blockIdx.y;
    int b    = blockIdx.z;

    const __nv_bfloat16* Qh = g_QKVh + (size_t)(0 + part) * MTOT * 128;
    const __nv_bfloat16* Ql = g_QKVl + (size_t)(0 + part) * MTOT * 128;
    const __nv_bfloat16* Kh = g_QKVh + (size_t)(2 + part) * MTOT * 128;
    const __nv_bfloat16* Kl = g_QKVl + (size_t)(2 + part) * MTOT * 128;
    const __nv_bfloat16* Vh = g_QKVh + (size_t)(4 + part) * MTOT * 128;
    const __nv_bfloat16* Vl = g_QKVl + (size_t)(4 + part) * MTOT * 128;

    int qrowbase = b * LQ + pair * 128;      // 128 contiguous q rows
    const float SC = 0.08838834764831845f * 1.4426950408889634f;  // scale*log2(e)

    // ---- loaders ----
    auto load_q = [&]() {
#pragma unroll
        for (int i = 0; i < 16; i++) {
            int e = tid + i * 256;            // 0..4095
            int mat = e >> 11;                // 0=h, 1=l (2048 chunks each)
            int idx = e & 2047;
            int r = idx >> 4, c = idx & 15;   // 128 rows x 16 chunks
            const __nv_bfloat16* src = (mat ? Ql : Qh) + (size_t)(qrowbase + r) * 128 + c * 8;
            cp16(sb + (uint32_t)(mat * QMATB) + (uint32_t)(r * AST + c * 8) * 2, src);
        }
    };
    auto load_kv = [&](int kb, int s) {
        int krow0 = b * LQ + kb * 64;
        uint32_t stb = sb + (uint32_t)(2 * QMATB + 4 * s * AMATB);
#pragma unroll
        for (int i = 0; i < 16; i++) {
            int e = tid + i * 256;            // 0..4095
            int mat = e >> 10;                // 0=Kh 1=Kl 2=Vh 3=Vl
            int idx = e & 1023;
            int r = idx >> 4, c = idx & 15;
            const __nv_bfloat16* src;
            if (mat == 0) src = Kh; else if (mat == 1) src = Kl;
            else if (mat == 2) src = Vh; else src = Vl;
            src += (size_t)(krow0 + r) * 128 + c * 8;
            cp16(stb + (uint32_t)(mat * AMATB) + (uint32_t)(r * AST + c * 8) * 2, src);
        }
    };

    float O[16][4];
#pragma unroll
    for (int nf = 0; nf < 16; nf++)
#pragma unroll
        for (int j = 0; j < 4; j++) O[nf][j] = 0.f;
    float m2_0 = -1e30f, m2_1 = -1e30f;
    float l0 = 0.f, l1 = 0.f;

    int cnt = g_ucnt[pair];
    const int* list = g_ulist[pair];
    const int* flg  = g_uflg[pair];

    load_q(); load_kv(list[0], 0); CP_COMMIT();
    if (cnt > 1) { load_kv(list[1], 1); CP_COMMIT(); }
    if (cnt > 1) { CP_WAIT(1); } else { CP_WAIT(0); }
    __syncthreads();

    int li = lane & 15;
    uint32_t a_off  = (uint32_t)((warp * 16 + li) * AST + (lane >> 4) * 8) * 2;
    uint32_t kv_row = (uint32_t)(li * AST + (lane >> 4) * 8) * 2;

    for (int i = 0; i < cnt; i++) {
        int s = i & 1;
        uint32_t sK = sb + (uint32_t)(2 * QMATB + 4 * s * AMATB);
        uint32_t sV = sK + 2 * AMATB;
        bool active = (flg[i] >> grp) & 1;

        if (active) {
            // ---- S = Q @ K^T (3-term) ----
            float sv[8][4];
#pragma unroll
            for (int nf = 0; nf < 8; nf++)
#pragma unroll
                for (int j = 0; j < 4; j++) sv[nf][j] = 0.f;

#pragma unroll
            for (int kd = 0; kd < 8; kd++) {
                uint32_t qaddr = sb + a_off + (uint32_t)(kd * 16) * 2;
                uint32_t aH[4], aL[4];
                ldmx4(aH, qaddr);
                ldmx4(aL, qaddr + QMATB);
#pragma unroll
                for (int jg = 0; jg < 4; jg++) {
                    uint32_t kaddr = sK + kv_row
                                   + (uint32_t)(jg * 16 * AST + kd * 16) * 2;
                    uint32_t bH[4], bL[4];
                    ldmx4(bH, kaddr);
                    ldmx4(bL, kaddr + AMATB);
                    mma_bf16(sv[jg * 2],     aH, bH[0], bH[2]);
                    mma_bf16(sv[jg * 2],     aH, bL[0], bL[2]);
                    mma_bf16(sv[jg * 2],     aL, bH[0], bH[2]);
                    mma_bf16(sv[jg * 2 + 1], aH, bH[1], bH[3]);
                    mma_bf16(sv[jg * 2 + 1], aH, bL[1], bL[3]);
                    mma_bf16(sv[jg * 2 + 1], aL, bH[1], bH[3]);
                }
            }

            // ---- online softmax (log2 domain) ----
            float mx0 = -1e30f, mx1 = -1e30f;
#pragma unroll
            for (int nf = 0; nf < 8; nf++) {
#pragma unroll
                for (int j = 0; j < 4; j++) sv[nf][j] *= SC;
                mx0 = fmaxf(mx0, fmaxf(sv[nf][0], sv[nf][1]));
                mx1 = fmaxf(mx1, fmaxf(sv[nf][2], sv[nf][3]));
            }
            mx0 = fmaxf(mx0, __shfl_xor_sync(0xffffffffu, mx0, 1));
            mx0 = fmaxf(mx0, __shfl_xor_sync(0xffffffffu, mx0, 2));
            mx1 = fmaxf(mx1, __shfl_xor_sync(0xffffffffu, mx1, 1));
            mx1 = fmaxf(mx1, __shfl_xor_sync(0xffffffffu, mx1, 2));

            float m0n = fmaxf(m2_0, mx0);
            float m1n = fmaxf(m2_1, mx1);
            float cor0 = exp2f(m2_0 - m0n);
            float cor1 = exp2f(m2_1 - m1n);
            m2_0 = m0n; m2_1 = m1n;

            uint32_t ph[8][2], pl[8][2];
            float ls0 = 0.f, ls1 = 0.f;
#pragma unroll
            for (int nf = 0; nf < 8; nf++) {
                float p0 = exp2f(sv[nf][0] - m0n);
                float p1 = exp2f(sv[nf][1] - m0n);
                float p2 = exp2f(sv[nf][2] - m1n);
                float p3 = exp2f(sv[nf][3] - m1n);
                ls0 += p0 + p1; ls1 += p2 + p3;
                split2(p0, p1, ph[nf][0], pl[nf][0]);
                split2(p2, p3, ph[nf][1], pl[nf][1]);
            }
            ls0 += __shfl_xor_sync(0xffffffffu, ls0, 1);
            ls0 += __shfl_xor_sync(0xffffffffu, ls0, 2);
            ls1 += __shfl_xor_sync(0xffffffffu, ls1, 1);
            ls1 += __shfl_xor_sync(0xffffffffu, ls1, 2);
            l0 = l0 * cor0 + ls0;
            l1 = l1 * cor1 + ls1;

            // ---- rescale O ----
#pragma unroll
            for (int nf = 0; nf < 16; nf++) {
                O[nf][0] *= cor0; O[nf][1] *= cor0;
                O[nf][2] *= cor1; O[nf][3] *= cor1;
            }

            // ---- O += P @ V (3-term) ----
#pragma unroll
            for (int kk = 0; kk < 4; kk++) {
                uint32_t aH[4] = {ph[2*kk][0], ph[2*kk][1], ph[2*kk+1][0], ph[2*kk+1][1]};
                uint32_t aL[4] = {pl[2*kk][0], pl[2*kk][1], pl[2*kk+1][0], pl[2*kk+1][1]};
#pragma unroll
                for (int dg = 0; dg < 8; dg++) {
                    uint32_t vaddr = sV + kv_row
                                   + (uint32_t)(kk * 16 * AST + dg * 16) * 2;
                    uint32_t vH[4], vL[4];
                    ldmx4t(vH, vaddr);
                    ldmx4t(vL, vaddr + AMATB);
                    mma_bf16(O[dg * 2],     aH, vH[0], vH[1]);
                    mma_bf16(O[dg * 2],     aH, vL[0], vL[1]);
                    mma_bf16(O[dg * 2],     aL, vH[0], vH[1]);
                    mma_bf16(O[dg * 2 + 1], aH, vH[2], vH[3]);
                    mma_bf16(O[dg * 2 + 1], aH, vL[2], vL[3]);
                    mma_bf16(O[dg * 2 + 1], aL, vH[2], vH[3]);
                }
            }
        }

        __syncthreads();
        if (i + 2 < cnt) { load_kv(list[i + 2], s); CP_COMMIT(); }
        if (i + 1 < cnt) {
            if (i + 2 < cnt) { CP_WAIT(1); } else { CP_WAIT(0); }
            __syncthreads();
        }
    }

    // ---- epilogue: normalized output as bf16 hi/lo ----
    float inv0 = 1.f / l0, inv1 = 1.f / l1;
    int r0 = qrowbase + warp * 16 + (lane >> 2);
    int r1 = r0 + 8;
#pragma unroll
    for (int nf = 0; nf < 16; nf++) {
        int col = part * 128 + nf * 8 + (lane & 3) * 2;
        uint32_t wh, wl;
        split2(O[nf][0] * inv0, O[nf][1] * inv0, wh, wl);
        *(uint32_t*)(g_Ath + (size_t)r0 * 256 + col) = wh;
        *(uint32_t*)(g_Atl + (size_t)r0 * 256 + col) = wl;
        split2(O[nf][2] * inv1, O[nf][3] * inv1, wh, wl);
        *(uint32_t*)(g_Ath + (size_t)r1 * 256 + col) = wh;
        *(uint32_t*)(g_Atl + (size_t)r1 * 256 + col) = wl;
    }
}

// ---------------------------------------------------------------------------
// Launch
// ---------------------------------------------------------------------------
extern "C" void kernel_launch(void* const* d_in, const int* in_sizes, int n_in,
                              void* d_out, int out_size)
{
    const float* xin[6];
    for (int i = 0; i < 6; i++) xin[i] = (const float*)d_in[i];
    const float* W_qkv  = (const float*)d_in[6];
    const float* b_qkv  = (const float*)d_in[7];
    const float* W_out  = (const float*)d_in[8];
    const float* b_out  = (const float*)d_in[9];
    const void*  mask   = d_in[10];
    float* out = (float*)d_out;
    (void)in_sizes; (void)n_in; (void)out_size;

    cudaFuncSetAttribute(attn_mma, cudaFuncAttributeMaxDynamicSharedMemorySize,
                         ATT_SMEM);
    cudaFuncSetAttribute(gemm_mma_impl<0>, cudaFuncAttributeMaxDynamicSharedMemorySize,
                         GEMM_SMEM);
    cudaFuncSetAttribute(gemm_mma_impl<1>, cudaFuncAttributeMaxDynamicSharedMemorySize,
                         GEMM_SMEM);

    __nv_bfloat16 *Xh, *Xl, *Wqh, *Wql, *Ath, *Atl, *Woh, *Wol;
    cudaGetSymbolAddress((void**)&Xh,  g_Xh);
    cudaGetSymbolAddress((void**)&Xl,  g_Xl);
    cudaGetSymbolAddress((void**)&Wqh, g_Wqh);
    cudaGetSymbolAddress((void**)&Wql, g_Wql);
    cudaGetSymbolAddress((void**)&Ath, g_Ath);
    cudaGetSymbolAddress((void**)&Atl, g_Atl);
    cudaGetSymbolAddress((void**)&Woh, g_Woh);
    cudaGetSymbolAddress((void**)&Wol, g_Wol);

    // launch order fixed so ncu (-s 5 -c 1) captures attn_mma
    build_mask_kernel<<<1, NPAIR>>>(mask);                                // 0
    split6_kernel<<<dim3(PLANE4 / 256, 6), 256>>>(                        // 1
        (const float4*)xin[0], (const float4*)xin[1], (const float4*)xin[2],
        (const float4*)xin[3], (const float4*)xin[4], (const float4*)xin[5],
        (uint2*)Xh, (uint2*)Xl);
    split_kernel<<<(768 * 768 / 4 + 255) / 256, 256>>>((const float4*)W_qkv,
        (uint2*)Wqh, (uint2*)Wql, 768 * 768 / 4);                         // 2
    split_kernel<<<(256 * 256 / 4 + 255) / 256, 256>>>((const float4*)W_out,
        (uint2*)Woh, (uint2*)Wol, 256 * 256 / 4);                         // 3
    gemm_mma_impl<0><<<dim3(6, MTOT / 128), 256, GEMM_SMEM>>>(            // 4
        Xh, Xl, Wqh, Wql, b_qkv, nullptr);
    attn_mma<<<dim3(NPAIR, 2, BQ), 256, ATT_SMEM>>>();                    // 5 <- ncu
    gemm_mma_impl<1><<<dim3(2, MTOT / 128), 256, GEMM_SMEM>>>(            // 6
        Ath, Atl, Woh, Wol, b_out, out);
}

// round 7
// speedup vs baseline: 1.0629x; 1.0629x over previous
#include <cuda_runtime.h>
#include <cuda_bf16.h>
#include <math_constants.h>
#include <cstdint>

// Problem constants
#define BQ   4
#define LQ   4096
#define DQ   128
#define NBQ  64
#define MTOT (BQ * LQ)     // 16384 rows

// ---------------------------------------------------------------------------
// Scratch (__device__ globals; no allocations allowed)
// ---------------------------------------------------------------------------
__device__ __nv_bfloat16 g_Xh[6 * MTOT * DQ];       // input hi/lo split (plane-major)
__device__ __nv_bfloat16 g_Xl[6 * MTOT * DQ];
__device__ __nv_bfloat16 g_Wqh[768 * 768];
__device__ __nv_bfloat16 g_Wql[768 * 768];
__device__ __nv_bfloat16 g_QKVh[6 * MTOT * DQ];     // QKV projection out, hi/lo
__device__ __nv_bfloat16 g_QKVl[6 * MTOT * DQ];
__device__ __nv_bfloat16 g_Ath[MTOT * 256];         // attention out, hi/lo
__device__ __nv_bfloat16 g_Atl[MTOT * 256];
__device__ __nv_bfloat16 g_Woh[256 * 256];
__device__ __nv_bfloat16 g_Wol[256 * 256];
__device__ int g_cnt[NBQ];
__device__ int g_list[NBQ][NBQ];

// ---------------------------------------------------------------------------
// Helpers
// ---------------------------------------------------------------------------
__device__ __forceinline__ uint32_t smem_to_u32(const void* p) {
    uint32_t a;
    asm("{ .reg .u64 t; cvta.to.shared.u64 t, %1; cvt.u32.u64 %0, t; }" : "=r"(a) : "l"(p));
    return a;
}
__device__ __forceinline__ void cp16(uint32_t dst_smem, const void* src) {
    asm volatile("cp.async.cg.shared.global [%0], [%1], 16;" :: "r"(dst_smem), "l"(src));
}
#define CP_COMMIT() asm volatile("cp.async.commit_group;" ::: "memory")
#define CP_WAIT(n)  asm volatile("cp.async.wait_group %0;" :: "n"(n) : "memory")

__device__ __forceinline__ void ldmx4(uint32_t* r, uint32_t addr) {
    asm volatile("ldmatrix.sync.aligned.m8n8.x4.shared.b16 {%0,%1,%2,%3}, [%4];"
                 : "=r"(r[0]), "=r"(r[1]), "=r"(r[2]), "=r"(r[3]) : "r"(addr));
}
__device__ __forceinline__ void ldmx4t(uint32_t* r, uint32_t addr) {
    asm volatile("ldmatrix.sync.aligned.m8n8.x4.trans.shared.b16 {%0,%1,%2,%3}, [%4];"
                 : "=r"(r[0]), "=r"(r[1]), "=r"(r[2]), "=r"(r[3]) : "r"(addr));
}
__device__ __forceinline__ void ldmx2(uint32_t* r, uint32_t addr) {
    asm volatile("ldmatrix.sync.aligned.m8n8.x2.shared.b16 {%0,%1}, [%2];"
                 : "=r"(r[0]), "=r"(r[1]) : "r"(addr));
}
__device__ __forceinline__ void mma_bf16(float* c, const uint32_t* a,
                                         uint32_t b0, uint32_t b1) {
    asm volatile(
        "mma.sync.aligned.m16n8k16.row.col.f32.bf16.bf16.f32 "
        "{%0,%1,%2,%3}, {%4,%5,%6,%7}, {%8,%9}, {%0,%1,%2,%3};"
        : "+f"(c[0]), "+f"(c[1]), "+f"(c[2]), "+f"(c[3])
        : "r"(a[0]), "r"(a[1]), "r"(a[2]), "r"(a[3]), "r"(b0), "r"(b1));
}
__device__ __forceinline__ uint32_t pack_bf2(float a, float b) {
    __nv_bfloat162 t = __floats2bfloat162_rn(a, b);
    return *(uint32_t*)&t;
}
__device__ __forceinline__ void split2(float a, float b, uint32_t& h, uint32_t& l) {
    __nv_bfloat16 ha = __float2bfloat16(a);
    __nv_bfloat16 hb = __float2bfloat16(b);
    h = ((uint32_t)__bfloat16_as_ushort(hb) << 16) | __bfloat16_as_ushort(ha);
    l = pack_bf2(a - __bfloat162float(ha), b - __bfloat162float(hb));
}

// ---------------------------------------------------------------------------
// Block-mask compaction (per-qblock lists)
// ---------------------------------------------------------------------------
__global__ void build_mask_kernel(const void* __restrict__ mask)
{
    int qb = threadIdx.x;
    if (qb >= NBQ) return;
    const float* mf = (const float*)mask;
    const int*   mi = (const int*)mask;
    const unsigned char* mb = (const unsigned char*)mask;
    int mode;
    if (mf[0] == 1.0f)   mode = 0;
    else if (mi[0] == 1) mode = 1;
    else                 mode = 2;
    int cnt = 0;
    for (int kb = 0; kb <= qb; kb++) {
        size_t idx = (size_t)(qb * 64) * (size_t)LQ + (size_t)(kb * 64);
        bool on;
        if (mode == 0)      on = (mf[idx] != 0.0f);
        else if (mode == 1) on = (mi[idx] != 0);
        else                on = (mb[idx] != 0);
        if (on) g_list[qb][cnt++] = kb;
    }
    g_cnt[qb] = cnt;
}

// ---------------------------------------------------------------------------
// fp32 -> bf16 hi/lo split: all 6 input planes in one launch (grid.y=plane)
// ---------------------------------------------------------------------------
#define PLANE4 (MTOT * DQ / 4)
__global__ void split6_kernel(
    const float4* __restrict__ s0, const float4* __restrict__ s1,
    const float4* __restrict__ s2, const float4* __restrict__ s3,
    const float4* __restrict__ s4, const float4* __restrict__ s5,
    uint2* __restrict__ hi, uint2* __restrict__ lo)
{
    int plane = blockIdx.y;
    const float4* src = (plane == 0) ? s0 : (plane == 1) ? s1 : (plane == 2) ? s2
                      : (plane == 3) ? s3 : (plane == 4) ? s4 : s5;
    int i = blockIdx.x * 256 + threadIdx.x;     // PLANE4 exact multiple of 256
    float4 v = src[i];
    float f[4] = {v.x, v.y, v.z, v.w};
    uint32_t hw[4], lw[4];
#pragma unroll
    for (int j = 0; j < 4; j++) {
        __nv_bfloat16 h = __float2bfloat16(f[j]);
        __nv_bfloat16 l = __float2bfloat16(f[j] - __bfloat162float(h));
        hw[j] = (uint32_t)__bfloat16_as_ushort(h);
        lw[j] = (uint32_t)__bfloat16_as_ushort(l);
    }
    size_t o = (size_t)plane * PLANE4 + i;
    hi[o] = make_uint2((hw[1] << 16) | hw[0], (hw[3] << 16) | hw[2]);
    lo[o] = make_uint2((lw[1] << 16) | lw[0], (lw[3] << 16) | lw[2]);
}

// single-tensor split (weights)
__global__ void split_kernel(const float4* __restrict__ src,
                             uint2* __restrict__ hi, uint2* __restrict__ lo, int n4)
{
    int i = blockIdx.x * 256 + threadIdx.x;
    if (i >= n4) return;
    float4 v = src[i];
    float f[4] = {v.x, v.y, v.z, v.w};
    uint32_t hw[4], lw[4];
#pragma unroll
    for (int j = 0; j < 4; j++) {
        __nv_bfloat16 h = __float2bfloat16(f[j]);
        __nv_bfloat16 l = __float2bfloat16(f[j] - __bfloat162float(h));
        hw[j] = (uint32_t)__bfloat16_as_ushort(h);
        lw[j] = (uint32_t)__bfloat16_as_ushort(l);
    }
    hi[i] = make_uint2((hw[1] << 16) | hw[0], (hw[3] << 16) | hw[2]);
    lo[i] = make_uint2((lw[1] << 16) | lw[0], (lw[3] << 16) | lw[2]);
}

// ---------------------------------------------------------------------------
// HMMA GEMM (3-term bf16 hi/lo split). Tile 128x128x32, 8 warps.
// MODE 0: QKV (K=768) -> writes bf16 hi/lo planes g_QKVh/g_QKVl
// MODE 1: OUT (K=256) -> writes fp32 halves of d_out
// ---------------------------------------------------------------------------
#define GSTRIDE 40
#define MATE    (128 * GSTRIDE)
#define MATB    (MATE * 2)
#define STAGEB  (4 * MATB)
#define GEMM_SMEM (2 * STAGEB)

template<int MODE>
__global__ __launch_bounds__(256, 1) void gemm_mma_impl(
    const __nv_bfloat16* __restrict__ Ah, const __nv_bfloat16* __restrict__ Al,
    const __nv_bfloat16* __restrict__ Bh, const __nv_bfloat16* __restrict__ Bl,
    const float* __restrict__ bias, float* __restrict__ Cout)
{
    constexpr int KTOT = (MODE == 0) ? 768 : 256;
    constexpr int NCH  = KTOT / 32;

    extern __shared__ __align__(128) char smc[];
    uint32_t sbase0 = smem_to_u32(smc);

    int tid  = threadIdx.x;
    int warp = tid >> 5, lane = tid & 31;
    int wm = warp & 1;
    int wn = warp >> 1;
    int m0 = blockIdx.y * 128;
    int n0 = blockIdx.x * 128;

    auto load_stage = [&](int ch, int buf) {
        int k0 = ch * 32;
        uint32_t sb = sbase0 + buf * STAGEB;
#pragma unroll
        for (int i = 0; i < 2; i++) {
            int e = tid + i * 256;
            int r = e >> 2, seg = e & 3;
            uint32_t off = (uint32_t)(r * GSTRIDE + seg * 8) * 2;
            size_t ga;
            if (MODE == 0) ga = ((size_t)(k0 >> 7) * MTOT + m0 + r) * 128 + (k0 & 127) + seg * 8;
            else           ga = (size_t)(m0 + r) * KTOT + k0 + seg * 8;
            cp16(sb + off,            Ah + ga);
            cp16(sb + MATB + off,     Al + ga);
            size_t gb = (size_t)(n0 + r) * KTOT + k0 + seg * 8;
            cp16(sb + 2 * MATB + off, Bh + gb);
            cp16(sb + 3 * MATB + off, Bl + gb);
        }
    };

    float acc[4][4][4];
#pragma unroll
    for (int mf = 0; mf < 4; mf++)
#pragma unroll
        for (int nf = 0; nf < 4; nf++)
#pragma unroll
            for (int j = 0; j < 4; j++) acc[mf][nf][j] = 0.f;

    load_stage(0, 0); CP_COMMIT();
    load_stage(1, 1); CP_COMMIT();
    CP_WAIT(1);
    __syncthreads();

    int li = lane & 15;
    uint32_t a_row_off = (uint32_t)((wm * 64 + li) * GSTRIDE) * 2;
    uint32_t a_col_off = (uint32_t)((lane >> 4) * 8) * 2;
    uint32_t b_row_off = (uint32_t)((wn * 32 + (li & 7)) * GSTRIDE) * 2;
    uint32_t b_col_off = (uint32_t)((li >> 3) * 8) * 2;

    for (int ch = 0; ch < NCH; ch++) {
        uint32_t sb = sbase0 + (ch & 1) * STAGEB;
#pragma unroll
        for (int k16 = 0; k16 < 2; k16++) {
            uint32_t kofs = (uint32_t)(k16 * 16) * 2;
            uint32_t ah[4][4], al[4][4];
#pragma unroll
            for (int mf = 0; mf < 4; mf++) {
                uint32_t addr = sb + a_row_off
                              + (uint32_t)(mf * 16 * GSTRIDE * 2) + kofs + a_col_off;
                ldmx4(ah[mf], addr);
                ldmx4(al[mf], addr + MATB);
            }
            uint32_t bh[4][2], bl[4][2];
#pragma unroll
            for (int nf = 0; nf < 4; nf++) {
                uint32_t addr = sb + 2 * MATB + b_row_off
                              + (uint32_t)(nf * 8 * GSTRIDE * 2) + kofs + b_col_off;
                ldmx2(bh[nf], addr);
                ldmx2(bl[nf], addr + MATB);
            }
#pragma unroll
            for (int mf = 0; mf < 4; mf++)
#pragma unroll
                for (int nf = 0; nf < 4; nf++) {
                    mma_bf16(acc[mf][nf], ah[mf], bh[nf][0], bh[nf][1]);
                    mma_bf16(acc[mf][nf], ah[mf], bl[nf][0], bl[nf][1]);
                    mma_bf16(acc[mf][nf], al[mf], bh[nf][0], bh[nf][1]);
                }
        }
        __syncthreads();
        if (ch + 2 < NCH) { load_stage(ch + 2, ch & 1); CP_COMMIT(); }
        if (ch + 1 < NCH) {
            if (ch + 2 < NCH) { CP_WAIT(1); } else { CP_WAIT(0); }
            __syncthreads();
        }
    }

    // epilogue
#pragma unroll
    for (int mf = 0; mf < 4; mf++) {
        int r0 = m0 + wm * 64 + mf * 16 + (lane >> 2);
#pragma unroll
        for (int nf = 0; nf < 4; nf++) {
            int cp = wn * 32 + nf * 8 + (lane & 3) * 2;
            float b0 = __ldg(bias + blockIdx.x * 128 + cp);
            float b1 = __ldg(bias + blockIdx.x * 128 + cp + 1);
            float v00 = acc[mf][nf][0] + b0, v01 = acc[mf][nf][1] + b1;
            float v10 = acc[mf][nf][2] + b0, v11 = acc[mf][nf][3] + b1;
            if (MODE == 0) {
                size_t base = (size_t)blockIdx.x * MTOT * 128;
                uint32_t w0h, w0l, w1h, w1l;
                split2(v00, v01, w0h, w0l);
                split2(v10, v11, w1h, w1l);
                *(uint32_t*)(g_QKVh + base + (size_t)r0 * 128 + cp)       = w0h;
                *(uint32_t*)(g_QKVl + base + (size_t)r0 * 128 + cp)       = w0l;
                *(uint32_t*)(g_QKVh + base + (size_t)(r0 + 8) * 128 + cp) = w1h;
                *(uint32_t*)(g_QKVl + base + (size_t)(r0 + 8) * 128 + cp) = w1l;
            } else {
                float* dst = Cout + (size_t)blockIdx.x * MTOT * 128;
                *(float2*)(dst + (size_t)r0 * 128 + cp)       = make_float2(v00, v01);
                *(float2*)(dst + (size_t)(r0 + 8) * 128 + cp) = make_float2(v10, v11);
            }
        }
    }
}

// ---------------------------------------------------------------------------
// HMMA block-sparse flash attention (64-query CTAs, 2 CTAs/SM).
// Grid (NBQ, 2, BQ); 128 threads = 4 warps x 16 query rows.
// Single-stage K/V smem (104 KB) -> 2 CTAs resident per SM; cross-CTA overlap
// hides cp.async fill + exposes 2 warps/SMSP for MMA/ldmatrix latency hiding.
// S and PV are 3-term bf16 hi/lo. Epilogue emits bf16 hi/lo (feeds out GEMM).
// ---------------------------------------------------------------------------
#define AST   136
#define AMATB (64 * AST * 2)            // 17408 bytes per 64x128 matrix
#define ATT_SMEM (6 * AMATB)            // Qh Ql Kh Kl Vh Vl = 104448 bytes

__global__ __launch_bounds__(128, 2) void attn_mma()
{
    extern __shared__ __align__(128) char sma[];
    uint32_t sb = smem_to_u32(sma);

    int tid  = threadIdx.x;
    int warp = tid >> 5, lane = tid & 31;
    int qb   = blockIdx.x;
    int part = blockIdx.y;
    int b    = blockIdx.z;

    const __nv_bfloat16* Qh = g_QKVh + (size_t)(0 + part) * MTOT * 128;
    const __nv_bfloat16* Ql = g_QKVl + (size_t)(0 + part) * MTOT * 128;
    const __nv_bfloat16* Kh = g_QKVh + (size_t)(2 + part) * MTOT * 128;
    const __nv_bfloat16* Kl = g_QKVl + (size_t)(2 + part) * MTOT * 128;
    const __nv_bfloat16* Vh = g_QKVh + (size_t)(4 + part) * MTOT * 128;
    const __nv_bfloat16* Vl = g_QKVl + (size_t)(4 + part) * MTOT * 128;

    int qrow0 = b * LQ + qb * 64;
    const float SC = 0.08838834764831845f * 1.4426950408889634f;  // scale*log2(e)

    // ---- loaders: each 64x128 bf16 matrix = 1024 16B chunks ----
    auto load_q = [&]() {
#pragma unroll
        for (int i = 0; i < 16; i++) {
            int e = tid + i * 128;            // 0..2047
            int mat = e >> 10;                // 0=h, 1=l
            int idx = e & 1023;
            int r = idx >> 4, c = idx & 15;
            const __nv_bfloat16* src = (mat ? Ql : Qh) + (size_t)(qrow0 + r) * 128 + c * 8;
            cp16(sb + (uint32_t)(mat * AMATB) + (uint32_t)(r * AST + c * 8) * 2, src);
        }
    };
    auto load_kv = [&](int kb) {
        int krow0 = b * LQ + kb * 64;
        uint32_t stb = sb + (uint32_t)(2 * AMATB);
#pragma unroll
        for (int i = 0; i < 32; i++) {
            int e = tid + i * 128;            // 0..4095
            int mat = e >> 10;                // 0=Kh 1=Kl 2=Vh 3=Vl
            int idx = e & 1023;
            int r = idx >> 4, c = idx & 15;
            const __nv_bfloat16* src;
            if (mat == 0) src = Kh; else if (mat == 1) src = Kl;
            else if (mat == 2) src = Vh; else src = Vl;
            src += (size_t)(krow0 + r) * 128 + c * 8;
            cp16(stb + (uint32_t)(mat * AMATB) + (uint32_t)(r * AST + c * 8) * 2, src);
        }
    };

    float O[16][4];
#pragma unroll
    for (int nf = 0; nf < 16; nf++)
#pragma unroll
        for (int j = 0; j < 4; j++) O[nf][j] = 0.f;
    float m2_0 = -1e30f, m2_1 = -1e30f;
    float l0 = 0.f, l1 = 0.f;

    int cnt = g_cnt[qb];
    const int* list = g_list[qb];

    load_q(); load_kv(list[0]); CP_COMMIT();

    int li = lane & 15;
    uint32_t a_off  = (uint32_t)((warp * 16 + li) * AST + (lane >> 4) * 8) * 2;
    uint32_t kv_row = (uint32_t)(li * AST + (lane >> 4) * 8) * 2;
    uint32_t sK = sb + 2 * AMATB;
    uint32_t sV = sb + 4 * AMATB;

    for (int i = 0; i < cnt; i++) {
        CP_WAIT(0);
        __syncthreads();

        // ---- S = Q @ K^T (3-term) ----
        float sv[8][4];
#pragma unroll
        for (int nf = 0; nf < 8; nf++)
#pragma unroll
            for (int j = 0; j < 4; j++) sv[nf][j] = 0.f;

#pragma unroll
        for (int kd = 0; kd < 8; kd++) {
            uint32_t qaddr = sb + a_off + (uint32_t)(kd * 16) * 2;
            uint32_t aH[4], aL[4];
            ldmx4(aH, qaddr);
            ldmx4(aL, qaddr + AMATB);
#pragma unroll
            for (int jg = 0; jg < 4; jg++) {
                uint32_t kaddr = sK + kv_row
                               + (uint32_t)(jg * 16 * AST + kd * 16) * 2;
                uint32_t bH[4], bL[4];
                ldmx4(bH, kaddr);
                ldmx4(bL, kaddr + AMATB);
                mma_bf16(sv[jg * 2],     aH, bH[0], bH[2]);
                mma_bf16(sv[jg * 2],     aH, bL[0], bL[2]);
                mma_bf16(sv[jg * 2],     aL, bH[0], bH[2]);
                mma_bf16(sv[jg * 2 + 1], aH, bH[1], bH[3]);
                mma_bf16(sv[jg * 2 + 1], aH, bL[1], bL[3]);
                mma_bf16(sv[jg * 2 + 1], aL, bH[1], bH[3]);
            }
        }

        // ---- online softmax (log2 domain) ----
        float mx0 = -1e30f, mx1 = -1e30f;
#pragma unroll
        for (int nf = 0; nf < 8; nf++) {
#pragma unroll
            for (int j = 0; j < 4; j++) sv[nf][j] *= SC;
            mx0 = fmaxf(mx0, fmaxf(sv[nf][0], sv[nf][1]));
            mx1 = fmaxf(mx1, fmaxf(sv[nf][2], sv[nf][3]));
        }
        mx0 = fmaxf(mx0, __shfl_xor_sync(0xffffffffu, mx0, 1));
        mx0 = fmaxf(mx0, __shfl_xor_sync(0xffffffffu, mx0, 2));
        mx1 = fmaxf(mx1, __shfl_xor_sync(0xffffffffu, mx1, 1));
        mx1 = fmaxf(mx1, __shfl_xor_sync(0xffffffffu, mx1, 2));

        float m0n = fmaxf(m2_0, mx0);
        float m1n = fmaxf(m2_1, mx1);
        float cor0 = exp2f(m2_0 - m0n);
        float cor1 = exp2f(m2_1 - m1n);
        m2_0 = m0n; m2_1 = m1n;

        uint32_t ph[8][2], pl[8][2];
        float ls0 = 0.f, ls1 = 0.f;
#pragma unroll
        for (int nf = 0; nf < 8; nf++) {
            float p0 = exp2f(sv[nf][0] - m0n);
            float p1 = exp2f(sv[nf][1] - m0n);
            float p2 = exp2f(sv[nf][2] - m1n);
            float p3 = exp2f(sv[nf][3] - m1n);
            ls0 += p0 + p1; ls1 += p2 + p3;
            split2(p0, p1, ph[nf][0], pl[nf][0]);
            split2(p2, p3, ph[nf][1], pl[nf][1]);
        }
        ls0 += __shfl_xor_sync(0xffffffffu, ls0, 1);
        ls0 += __shfl_xor_sync(0xffffffffu, ls0, 2);
        ls1 += __shfl_xor_sync(0xffffffffu, ls1, 1);
        ls1 += __shfl_xor_sync(0xffffffffu, ls1, 2);
        l0 = l0 * cor0 + ls0;
        l1 = l1 * cor1 + ls1;

        // ---- rescale O ----
#pragma unroll
        for (int nf = 0; nf < 16; nf++) {
            O[nf][0] *= cor0; O[nf][1] *= cor0;
            O[nf][2] *= cor1; O[nf][3] *= cor1;
        }

        // ---- O += P @ V (3-term) ----
#pragma unroll
        for (int kk = 0; kk < 4; kk++) {
            uint32_t aH[4] = {ph[2*kk][0], ph[2*kk][1], ph[2*kk+1][0], ph[2*kk+1][1]};
            uint32_t aL[4] = {pl[2*kk][0], pl[2*kk][1], pl[2*kk+1][0], pl[2*kk+1][1]};
#pragma unroll
            for (int dg = 0; dg < 8; dg++) {
                uint32_t vaddr = sV + kv_row
                               + (uint32_t)(kk * 16 * AST + dg * 16) * 2;
                uint32_t vH[4], vL[4];
                ldmx4t(vH, vaddr);
                ldmx4t(vL, vaddr + AMATB);
                mma_bf16(O[dg * 2],     aH, vH[0], vH[1]);
                mma_bf16(O[dg * 2],     aH, vL[0], vL[1]);
                mma_bf16(O[dg * 2],     aL, vH[0], vH[1]);
                mma_bf16(O[dg * 2 + 1], aH, vH[2], vH[3]);
                mma_bf16(O[dg * 2 + 1], aH, vL[2], vL[3]);
                mma_bf16(O[dg * 2 + 1], aL, vH[2], vH[3]);
            }
        }

        __syncthreads();
        if (i + 1 < cnt) { load_kv(list[i + 1]); CP_COMMIT(); }
    }

    // ---- epilogue: normalized output as bf16 hi/lo ----
    float inv0 = 1.f / l0, inv1 = 1.f / l1;
    int r0 = qrow0 + warp * 16 + (lane >> 2);
    int r1 = r0 + 8;
#pragma unroll
    for (int nf = 0; nf < 16; nf++) {
        int col = part * 128 + nf * 8 + (lane & 3) * 2;
        uint32_t wh, wl;
        split2(O[nf][0] * inv0, O[nf][1] * inv0, wh, wl);
        *(uint32_t*)(g_Ath + (size_t)r0 * 256 + col) = wh;
        *(uint32_t*)(g_Atl + (size_t)r0 * 256 + col) = wl;
        split2(O[nf][2] * inv1, O[nf][3] * inv1, wh, wl);
        *(uint32_t*)(g_Ath + (size_t)r1 * 256 + col) = wh;
        *(uint32_t*)(g_Atl + (size_t)r1 * 256 + col) = wl;
    }
}

// ---------------------------------------------------------------------------
// Launch
// ---------------------------------------------------------------------------
extern "C" void kernel_launch(void* const* d_in, const int* in_sizes, int n_in,
                              void* d_out, int out_size)
{
    const float* xin[6];
    for (int i = 0; i < 6; i++) xin[i] = (const float*)d_in[i];
    const float* W_qkv  = (const float*)d_in[6];
    const float* b_qkv  = (const float*)d_in[7];
    const float* W_out  = (const float*)d_in[8];
    const float* b_out  = (const float*)d_in[9];
    const void*  mask   = d_in[10];
    float* out = (float*)d_out;
    (void)in_sizes; (void)n_in; (void)out_size;

    cudaFuncSetAttribute(attn_mma, cudaFuncAttributeMaxDynamicSharedMemorySize,
                         ATT_SMEM);
    cudaFuncSetAttribute(gemm_mma_impl<0>, cudaFuncAttributeMaxDynamicSharedMemorySize,
                         GEMM_SMEM);
    cudaFuncSetAttribute(gemm_mma_impl<1>, cudaFuncAttributeMaxDynamicSharedMemorySize,
                         GEMM_SMEM);

    __nv_bfloat16 *Xh, *Xl, *Wqh, *Wql, *Ath, *Atl, *Woh, *Wol;
    cudaGetSymbolAddress((void**)&Xh,  g_Xh);
    cudaGetSymbolAddress((void**)&Xl,  g_Xl);
    cudaGetSymbolAddress((void**)&Wqh, g_Wqh);
    cudaGetSymbolAddress((void**)&Wql, g_Wql);
    cudaGetSymbolAddress((void**)&Ath, g_Ath);
    cudaGetSymbolAddress((void**)&Atl, g_Atl);
    cudaGetSymbolAddress((void**)&Woh, g_Woh);
    cudaGetSymbolAddress((void**)&Wol, g_Wol);

    // launch order fixed so ncu (-s 5 -c 1) captures attn_mma
    build_mask_kernel<<<1, NBQ>>>(mask);                                  // 0
    split6_kernel<<<dim3(PLANE4 / 256, 6), 256>>>(                        // 1
        (const float4*)xin[0], (const float4*)xin[1], (const float4*)xin[2],
        (const float4*)xin[3], (const float4*)xin[4], (const float4*)xin[5],
        (uint2*)Xh, (uint2*)Xl);
    split_kernel<<<(768 * 768 / 4 + 255) / 256, 256>>>((const float4*)W_qkv,
        (uint2*)Wqh, (uint2*)Wql, 768 * 768 / 4);                         // 2
    split_kernel<<<(256 * 256 / 4 + 255) / 256, 256>>>((const float4*)W_out,
        (uint2*)Woh, (uint2*)Wol, 256 * 256 / 4);                         // 3
    gemm_mma_impl<0><<<dim3(6, MTOT / 128), 256, GEMM_SMEM>>>(            // 4
        Xh, Xl, Wqh, Wql, b_qkv, nullptr);
    attn_mma<<<dim3(NBQ, 2, BQ), 128, ATT_SMEM>>>();                      // 5 <- ncu
    gemm_mma_impl<1><<<dim3(2, MTOT / 128), 256, GEMM_SMEM>>>(            // 6
        Ath, Atl, Woh, Wol, b_out, out);
}

// round 8
// speedup vs baseline: 1.4344x; 1.3495x over previous
#include <cuda_runtime.h>
#include <cuda_bf16.h>
#include <cuda_fp16.h>
#include <math_constants.h>
#include <cstdint>

// Problem constants
#define BQ   4
#define LQ   4096
#define DQ   128
#define NBQ  64
#define MTOT (BQ * LQ)     // 16384 rows

// ---------------------------------------------------------------------------
// Scratch (__device__ globals; no allocations allowed)
// A-side operands are fp16 hi/lo (exact to ~2^-22); B-side single fp16.
// ---------------------------------------------------------------------------
__device__ __half g_Xh[6 * MTOT * DQ];       // input hi/lo split (plane-major)
__device__ __half g_Xl[6 * MTOT * DQ];
__device__ __half g_Wq[768 * 768];           // W_qkv, single fp16 (B operand)
__device__ __half g_QKVh[6 * MTOT * DQ];     // Q planes: hi; K/V planes: single
__device__ __half g_QKVl[6 * MTOT * DQ];     // Q planes: lo (K/V region unused)
__device__ __half g_Ath[MTOT * 256];         // attention out hi/lo (A operand)
__device__ __half g_Atl[MTOT * 256];
__device__ __half g_Wo[256 * 256];           // W_out, single fp16
__device__ int g_cnt[NBQ];
__device__ int g_list[NBQ][NBQ];

// ---------------------------------------------------------------------------
// Helpers
// ---------------------------------------------------------------------------
__device__ __forceinline__ uint32_t smem_to_u32(const void* p) {
    uint32_t a;
    asm("{ .reg .u64 t; cvta.to.shared.u64 t, %1; cvt.u32.u64 %0, t; }" : "=r"(a) : "l"(p));
    return a;
}
__device__ __forceinline__ void cp16(uint32_t dst_smem, const void* src) {
    asm volatile("cp.async.cg.shared.global [%0], [%1], 16;" :: "r"(dst_smem), "l"(src));
}
#define CP_COMMIT() asm volatile("cp.async.commit_group;" ::: "memory")
#define CP_WAIT(n)  asm volatile("cp.async.wait_group %0;" :: "n"(n) : "memory")

__device__ __forceinline__ void ldmx4(uint32_t* r, uint32_t addr) {
    asm volatile("ldmatrix.sync.aligned.m8n8.x4.shared.b16 {%0,%1,%2,%3}, [%4];"
                 : "=r"(r[0]), "=r"(r[1]), "=r"(r[2]), "=r"(r[3]) : "r"(addr));
}
__device__ __forceinline__ void ldmx4t(uint32_t* r, uint32_t addr) {
    asm volatile("ldmatrix.sync.aligned.m8n8.x4.trans.shared.b16 {%0,%1,%2,%3}, [%4];"
                 : "=r"(r[0]), "=r"(r[1]), "=r"(r[2]), "=r"(r[3]) : "r"(addr));
}
__device__ __forceinline__ void ldmx2(uint32_t* r, uint32_t addr) {
    asm volatile("ldmatrix.sync.aligned.m8n8.x2.shared.b16 {%0,%1}, [%2];"
                 : "=r"(r[0]), "=r"(r[1]) : "r"(addr));
}
__device__ __forceinline__ void mma_fp16(float* c, const uint32_t* a,
                                         uint32_t b0, uint32_t b1) {
    asm volatile(
        "mma.sync.aligned.m16n8k16.row.col.f32.f16.f16.f32 "
        "{%0,%1,%2,%3}, {%4,%5,%6,%7}, {%8,%9}, {%0,%1,%2,%3};"
        : "+f"(c[0]), "+f"(c[1]), "+f"(c[2]), "+f"(c[3])
        : "r"(a[0]), "r"(a[1]), "r"(a[2]), "r"(a[3]), "r"(b0), "r"(b1));
}
__device__ __forceinline__ uint32_t pack_h2(float a, float b) {
    __half2 t = __floats2half2_rn(a, b);
    return *(uint32_t*)&t;
}
__device__ __forceinline__ void split2h(float a, float b, uint32_t& h, uint32_t& l) {
    __half ha = __float2half_rn(a);
    __half hb = __float2half_rn(b);
    h = ((uint32_t)__half_as_ushort(hb) << 16) | __half_as_ushort(ha);
    l = pack_h2(a - __half2float(ha), b - __half2float(hb));
}

// ---------------------------------------------------------------------------
// Block-mask compaction (per-qblock lists)
// ---------------------------------------------------------------------------
__global__ void build_mask_kernel(const void* __restrict__ mask)
{
    int qb = threadIdx.x;
    if (qb >= NBQ) return;
    const float* mf = (const float*)mask;
    const int*   mi = (const int*)mask;
    const unsigned char* mb = (const unsigned char*)mask;
    int mode;
    if (mf[0] == 1.0f)   mode = 0;
    else if (mi[0] == 1) mode = 1;
    else                 mode = 2;
    int cnt = 0;
    for (int kb = 0; kb <= qb; kb++) {
        size_t idx = (size_t)(qb * 64) * (size_t)LQ + (size_t)(kb * 64);
        bool on;
        if (mode == 0)      on = (mf[idx] != 0.0f);
        else if (mode == 1) on = (mi[idx] != 0);
        else                on = (mb[idx] != 0);
        if (on) g_list[qb][cnt++] = kb;
    }
    g_cnt[qb] = cnt;
}

// ---------------------------------------------------------------------------
// fp32 -> fp16 hi/lo split: all 6 input planes in one launch
// ---------------------------------------------------------------------------
#define PLANE4 (MTOT * DQ / 4)
__global__ void split6_kernel(
    const float4* __restrict__ s0, const float4* __restrict__ s1,
    const float4* __restrict__ s2, const float4* __restrict__ s3,
    const float4* __restrict__ s4, const float4* __restrict__ s5,
    uint2* __restrict__ hi, uint2* __restrict__ lo)
{
    int plane = blockIdx.y;
    const float4* src = (plane == 0) ? s0 : (plane == 1) ? s1 : (plane == 2) ? s2
                      : (plane == 3) ? s3 : (plane == 4) ? s4 : s5;
    int i = blockIdx.x * 256 + threadIdx.x;
    float4 v = src[i];
    float f[4] = {v.x, v.y, v.z, v.w};
    uint32_t hw[4], lw[4];
#pragma unroll
    for (int j = 0; j < 4; j++) {
        __half h = __float2half_rn(f[j]);
        __half l = __float2half_rn(f[j] - __half2float(h));
        hw[j] = (uint32_t)__half_as_ushort(h);
        lw[j] = (uint32_t)__half_as_ushort(l);
    }
    size_t o = (size_t)plane * PLANE4 + i;
    hi[o] = make_uint2((hw[1] << 16) | hw[0], (hw[3] << 16) | hw[2]);
    lo[o] = make_uint2((lw[1] << 16) | lw[0], (lw[3] << 16) | lw[2]);
}

// fp32 -> single fp16 (weights, B operand)
__global__ void cvt_kernel(const float4* __restrict__ src,
                           uint2* __restrict__ dst, int n4)
{
    int i = blockIdx.x * 256 + threadIdx.x;
    if (i >= n4) return;
    float4 v = src[i];
    uint32_t w0 = pack_h2(v.x, v.y);
    uint32_t w1 = pack_h2(v.z, v.w);
    dst[i] = make_uint2(w0, w1);
}

// ---------------------------------------------------------------------------
// HMMA GEMM, fp16 2-term: D = Ah@B^T + Al@B^T (+bias).
// Tile 128x128x32, 8 warps, double-buffered cp.async.
// MODE 0: QKV (K=768). Output planes 0,1 (Q) -> fp16 hi/lo; planes 2..5
//         (K,V) -> single fp16 in g_QKVh.
// MODE 1: OUT (K=256) -> fp32 halves of d_out.
// ---------------------------------------------------------------------------
#define GSTRIDE 40
#define MATE    (128 * GSTRIDE)
#define MATB    (MATE * 2)           // 10240 bytes per matrix tile
#define STAGEB  (3 * MATB)           // Ah, Al, B = 30720
#define GEMM_SMEM (2 * STAGEB)       // 61440

template<int MODE>
__global__ __launch_bounds__(256, 1) void gemm_mma_impl(
    const __half* __restrict__ Ah, const __half* __restrict__ Al,
    const __half* __restrict__ B,
    const float* __restrict__ bias, float* __restrict__ Cout)
{
    constexpr int KTOT = (MODE == 0) ? 768 : 256;
    constexpr int NCH  = KTOT / 32;

    extern __shared__ __align__(128) char smc[];
    uint32_t sbase0 = smem_to_u32(smc);

    int tid  = threadIdx.x;
    int warp = tid >> 5, lane = tid & 31;
    int wm = warp & 1;
    int wn = warp >> 1;
    int m0 = blockIdx.y * 128;
    int n0 = blockIdx.x * 128;

    auto load_stage = [&](int ch, int buf) {
        int k0 = ch * 32;
        uint32_t sb = sbase0 + buf * STAGEB;
#pragma unroll
        for (int i = 0; i < 2; i++) {
            int e = tid + i * 256;
            int r = e >> 2, seg = e & 3;
            uint32_t off = (uint32_t)(r * GSTRIDE + seg * 8) * 2;
            size_t ga;
            if (MODE == 0) ga = ((size_t)(k0 >> 7) * MTOT + m0 + r) * 128 + (k0 & 127) + seg * 8;
            else           ga = (size_t)(m0 + r) * KTOT + k0 + seg * 8;
            cp16(sb + off,        Ah + ga);
            cp16(sb + MATB + off, Al + ga);
            size_t gb = (size_t)(n0 + r) * KTOT + k0 + seg * 8;
            cp16(sb + 2 * MATB + off, B + gb);
        }
    };

    float acc[4][4][4];
#pragma unroll
    for (int mf = 0; mf < 4; mf++)
#pragma unroll
        for (int nf = 0; nf < 4; nf++)
#pragma unroll
            for (int j = 0; j < 4; j++) acc[mf][nf][j] = 0.f;

    load_stage(0, 0); CP_COMMIT();
    load_stage(1, 1); CP_COMMIT();
    CP_WAIT(1);
    __syncthreads();

    int li = lane & 15;
    uint32_t a_row_off = (uint32_t)((wm * 64 + li) * GSTRIDE) * 2;
    uint32_t a_col_off = (uint32_t)((lane >> 4) * 8) * 2;
    uint32_t b_row_off = (uint32_t)((wn * 32 + (li & 7)) * GSTRIDE) * 2;
    uint32_t b_col_off = (uint32_t)((li >> 3) * 8) * 2;

    for (int ch = 0; ch < NCH; ch++) {
        uint32_t sb = sbase0 + (ch & 1) * STAGEB;
#pragma unroll
        for (int k16 = 0; k16 < 2; k16++) {
            uint32_t kofs = (uint32_t)(k16 * 16) * 2;
            uint32_t ah[4][4], al[4][4];
#pragma unroll
            for (int mf = 0; mf < 4; mf++) {
                uint32_t addr = sb + a_row_off
                              + (uint32_t)(mf * 16 * GSTRIDE * 2) + kofs + a_col_off;
                ldmx4(ah[mf], addr);
                ldmx4(al[mf], addr + MATB);
            }
            uint32_t bb[4][2];
#pragma unroll
            for (int nf = 0; nf < 4; nf++) {
                uint32_t addr = sb + 2 * MATB + b_row_off
                              + (uint32_t)(nf * 8 * GSTRIDE * 2) + kofs + b_col_off;
                ldmx2(bb[nf], addr);
            }
#pragma unroll
            for (int mf = 0; mf < 4; mf++)
#pragma unroll
                for (int nf = 0; nf < 4; nf++) {
                    mma_fp16(acc[mf][nf], ah[mf], bb[nf][0], bb[nf][1]);
                    mma_fp16(acc[mf][nf], al[mf], bb[nf][0], bb[nf][1]);
                }
        }
        __syncthreads();
        if (ch + 2 < NCH) { load_stage(ch + 2, ch & 1); CP_COMMIT(); }
        if (ch + 1 < NCH) {
            if (ch + 2 < NCH) { CP_WAIT(1); } else { CP_WAIT(0); }
            __syncthreads();
        }
    }

    // epilogue
#pragma unroll
    for (int mf = 0; mf < 4; mf++) {
        int r0 = m0 + wm * 64 + mf * 16 + (lane >> 2);
#pragma unroll
        for (int nf = 0; nf < 4; nf++) {
            int cp = wn * 32 + nf * 8 + (lane & 3) * 2;
            float b0 = __ldg(bias + blockIdx.x * 128 + cp);
            float b1 = __ldg(bias + blockIdx.x * 128 + cp + 1);
            float v00 = acc[mf][nf][0] + b0, v01 = acc[mf][nf][1] + b1;
            float v10 = acc[mf][nf][2] + b0, v11 = acc[mf][nf][3] + b1;
            if (MODE == 0) {
                size_t base = (size_t)blockIdx.x * MTOT * 128;
                if (blockIdx.x < 2) {
                    // Q planes: exact fp16 hi/lo (A operand of S)
                    uint32_t w0h, w0l, w1h, w1l;
                    split2h(v00, v01, w0h, w0l);
                    split2h(v10, v11, w1h, w1l);
                    *(uint32_t*)(g_QKVh + base + (size_t)r0 * 128 + cp)       = w0h;
                    *(uint32_t*)(g_QKVl + base + (size_t)r0 * 128 + cp)       = w0l;
                    *(uint32_t*)(g_QKVh + base + (size_t)(r0 + 8) * 128 + cp) = w1h;
                    *(uint32_t*)(g_QKVl + base + (size_t)(r0 + 8) * 128 + cp) = w1l;
                } else {
                    // K/V planes: single fp16 (B operand)
                    *(uint32_t*)(g_QKVh + base + (size_t)r0 * 128 + cp)       = pack_h2(v00, v01);
                    *(uint32_t*)(g_QKVh + base + (size_t)(r0 + 8) * 128 + cp) = pack_h2(v10, v11);
                }
            } else {
                float* dst = Cout + (size_t)blockIdx.x * MTOT * 128;
                *(float2*)(dst + (size_t)r0 * 128 + cp)       = make_float2(v00, v01);
                *(float2*)(dst + (size_t)(r0 + 8) * 128 + cp) = make_float2(v10, v11);
            }
        }
    }
}

// ---------------------------------------------------------------------------
// HMMA block-sparse flash attention, fp16 2-term.
// Grid (NBQ, 2, BQ); 128 threads (4 warps x 16 q rows); 2 CTAs/SM.
// smem: Qh, Ql + double-buffered (K, V) single fp16 = 6 * 17408 = 104448.
// S = [Qh;Ql] @ K^T (2 MMAs), PV with P split fp16 hi/lo, V single (2 MMAs).
// ---------------------------------------------------------------------------
#define AST   136
#define AMATB (64 * AST * 2)            // 17408 bytes per 64x128 matrix
#define ATT_SMEM (6 * AMATB)            // 104448

__global__ __launch_bounds__(128, 2) void attn_mma()
{
    extern __shared__ __align__(128) char sma[];
    uint32_t sb = smem_to_u32(sma);

    int tid  = threadIdx.x;
    int warp = tid >> 5, lane = tid & 31;
    int qb   = blockIdx.x;
    int part = blockIdx.y;
    int b    = blockIdx.z;

    const __half* Qh = g_QKVh + (size_t)(0 + part) * MTOT * 128;
    const __half* Ql = g_QKVl + (size_t)(0 + part) * MTOT * 128;
    const __half* Kp = g_QKVh + (size_t)(2 + part) * MTOT * 128;
    const __half* Vp = g_QKVh + (size_t)(4 + part) * MTOT * 128;

    int qrow0 = b * LQ + qb * 64;
    const float SC = 0.08838834764831845f * 1.4426950408889634f;  // scale*log2(e)

    // ---- loaders: each 64x128 fp16 matrix = 1024 16B chunks ----
    auto load_q = [&]() {
#pragma unroll
        for (int i = 0; i < 16; i++) {
            int e = tid + i * 128;            // 0..2047
            int mat = e >> 10;                // 0=Qh, 1=Ql
            int idx = e & 1023;
            int r = idx >> 4, c = idx & 15;
            const __half* src = (mat ? Ql : Qh) + (size_t)(qrow0 + r) * 128 + c * 8;
            cp16(sb + (uint32_t)(mat * AMATB) + (uint32_t)(r * AST + c * 8) * 2, src);
        }
    };
    auto load_kv = [&](int kb, int s) {
        int krow0 = b * LQ + kb * 64;
        uint32_t stb = sb + (uint32_t)((2 + 2 * s) * AMATB);
#pragma unroll
        for (int i = 0; i < 16; i++) {
            int e = tid + i * 128;            // 0..2047
            int mat = e >> 10;                // 0=K, 1=V
            int idx = e & 1023;
            int r = idx >> 4, c = idx & 15;
            const __half* src = (mat ? Vp : Kp) + (size_t)(krow0 + r) * 128 + c * 8;
            cp16(stb + (uint32_t)(mat * AMATB) + (uint32_t)(r * AST + c * 8) * 2, src);
        }
    };

    float O[16][4];
#pragma unroll
    for (int nf = 0; nf < 16; nf++)
#pragma unroll
        for (int j = 0; j < 4; j++) O[nf][j] = 0.f;
    float m2_0 = -1e30f, m2_1 = -1e30f;
    float l0 = 0.f, l1 = 0.f;

    int cnt = g_cnt[qb];
    const int* list = g_list[qb];

    load_q(); load_kv(list[0], 0); CP_COMMIT();
    if (cnt > 1) { load_kv(list[1], 1); CP_COMMIT(); }
    if (cnt > 1) { CP_WAIT(1); } else { CP_WAIT(0); }
    __syncthreads();

    int li = lane & 15;
    uint32_t a_off  = (uint32_t)((warp * 16 + li) * AST + (lane >> 4) * 8) * 2;
    uint32_t kv_row = (uint32_t)(li * AST + (lane >> 4) * 8) * 2;

    for (int i = 0; i < cnt; i++) {
        int s = i & 1;
        uint32_t sK = sb + (uint32_t)((2 + 2 * s) * AMATB);
        uint32_t sV = sK + AMATB;

        // ---- S = Q @ K^T (2-term fp16) ----
        float sv[8][4];
#pragma unroll
        for (int nf = 0; nf < 8; nf++)
#pragma unroll
            for (int j = 0; j < 4; j++) sv[nf][j] = 0.f;

#pragma unroll
        for (int kd = 0; kd < 8; kd++) {
            uint32_t qaddr = sb + a_off + (uint32_t)(kd * 16) * 2;
            uint32_t aH[4], aL[4];
            ldmx4(aH, qaddr);
            ldmx4(aL, qaddr + AMATB);
#pragma unroll
            for (int jg = 0; jg < 4; jg++) {
                uint32_t kaddr = sK + kv_row
                               + (uint32_t)(jg * 16 * AST + kd * 16) * 2;
                uint32_t bK[4];
                ldmx4(bK, kaddr);
                mma_fp16(sv[jg * 2],     aH, bK[0], bK[2]);
                mma_fp16(sv[jg * 2],     aL, bK[0], bK[2]);
                mma_fp16(sv[jg * 2 + 1], aH, bK[1], bK[3]);
                mma_fp16(sv[jg * 2 + 1], aL, bK[1], bK[3]);
            }
        }

        // ---- online softmax (log2 domain) ----
        float mx0 = -1e30f, mx1 = -1e30f;
#pragma unroll
        for (int nf = 0; nf < 8; nf++) {
#pragma unroll
            for (int j = 0; j < 4; j++) sv[nf][j] *= SC;
            mx0 = fmaxf(mx0, fmaxf(sv[nf][0], sv[nf][1]));
            mx1 = fmaxf(mx1, fmaxf(sv[nf][2], sv[nf][3]));
        }
        mx0 = fmaxf(mx0, __shfl_xor_sync(0xffffffffu, mx0, 1));
        mx0 = fmaxf(mx0, __shfl_xor_sync(0xffffffffu, mx0, 2));
        mx1 = fmaxf(mx1, __shfl_xor_sync(0xffffffffu, mx1, 1));
        mx1 = fmaxf(mx1, __shfl_xor_sync(0xffffffffu, mx1, 2));

        float m0n = fmaxf(m2_0, mx0);
        float m1n = fmaxf(m2_1, mx1);
        float cor0 = exp2f(m2_0 - m0n);
        float cor1 = exp2f(m2_1 - m1n);
        m2_0 = m0n; m2_1 = m1n;

        uint32_t ph[8][2], pl[8][2];
        float ls0 = 0.f, ls1 = 0.f;
#pragma unroll
        for (int nf = 0; nf < 8; nf++) {
            float p0 = exp2f(sv[nf][0] - m0n);
            float p1 = exp2f(sv[nf][1] - m0n);
            float p2 = exp2f(sv[nf][2] - m1n);
            float p3 = exp2f(sv[nf][3] - m1n);
            ls0 += p0 + p1; ls1 += p2 + p3;
            split2h(p0, p1, ph[nf][0], pl[nf][0]);
            split2h(p2, p3, ph[nf][1], pl[nf][1]);
        }
        ls0 += __shfl_xor_sync(0xffffffffu, ls0, 1);
        ls0 += __shfl_xor_sync(0xffffffffu, ls0, 2);
        ls1 += __shfl_xor_sync(0xffffffffu, ls1, 1);
        ls1 += __shfl_xor_sync(0xffffffffu, ls1, 2);
        l0 = l0 * cor0 + ls0;
        l1 = l1 * cor1 + ls1;

        // ---- rescale O ----
#pragma unroll
        for (int nf = 0; nf < 16; nf++) {
            O[nf][0] *= cor0; O[nf][1] *= cor0;
            O[nf][2] *= cor1; O[nf][3] *= cor1;
        }

        // ---- O += P @ V (2-term fp16) ----
#pragma unroll
        for (int kk = 0; kk < 4; kk++) {
            uint32_t aH[4] = {ph[2*kk][0], ph[2*kk][1], ph[2*kk+1][0], ph[2*kk+1][1]};
            uint32_t aL[4] = {pl[2*kk][0], pl[2*kk][1], pl[2*kk+1][0], pl[2*kk+1][1]};
#pragma unroll
            for (int dg = 0; dg < 8; dg++) {
                uint32_t vaddr = sV + kv_row
                               + (uint32_t)(kk * 16 * AST + dg * 16) * 2;
                uint32_t vV[4];
                ldmx4t(vV, vaddr);
                mma_fp16(O[dg * 2],     aH, vV[0], vV[1]);
                mma_fp16(O[dg * 2],     aL, vV[0], vV[1]);
                mma_fp16(O[dg * 2 + 1], aH, vV[2], vV[3]);
                mma_fp16(O[dg * 2 + 1], aL, vV[2], vV[3]);
            }
        }

        __syncthreads();
        if (i + 2 < cnt) { load_kv(list[i + 2], s); CP_COMMIT(); }
        if (i + 1 < cnt) {
            if (i + 2 < cnt) { CP_WAIT(1); } else { CP_WAIT(0); }
            __syncthreads();
        }
    }

    // ---- epilogue: normalized output as fp16 hi/lo (A operand of out GEMM) ----
    float inv0 = 1.f / l0, inv1 = 1.f / l1;
    int r0 = qrow0 + warp * 16 + (lane >> 2);
    int r1 = r0 + 8;
#pragma unroll
    for (int nf = 0; nf < 16; nf++) {
        int col = part * 128 + nf * 8 + (lane & 3) * 2;
        uint32_t wh, wl;
        split2h(O[nf][0] * inv0, O[nf][1] * inv0, wh, wl);
        *(uint32_t*)(g_Ath + (size_t)r0 * 256 + col) = wh;
        *(uint32_t*)(g_Atl + (size_t)r0 * 256 + col) = wl;
        split2h(O[nf][2] * inv1, O[nf][3] * inv1, wh, wl);
        *(uint32_t*)(g_Ath + (size_t)r1 * 256 + col) = wh;
        *(uint32_t*)(g_Atl + (size_t)r1 * 256 + col) = wl;
    }
}

// ---------------------------------------------------------------------------
// Launch
// ---------------------------------------------------------------------------
extern "C" void kernel_launch(void* const* d_in, const int* in_sizes, int n_in,
                              void* d_out, int out_size)
{
    const float* xin[6];
    for (int i = 0; i < 6; i++) xin[i] = (const float*)d_in[i];
    const float* W_qkv  = (const float*)d_in[6];
    const float* b_qkv  = (const float*)d_in[7];
    const float* W_out  = (const float*)d_in[8];
    const float* b_out  = (const float*)d_in[9];
    const void*  mask   = d_in[10];
    float* out = (float*)d_out;
    (void)in_sizes; (void)n_in; (void)out_size;

    cudaFuncSetAttribute(attn_mma, cudaFuncAttributeMaxDynamicSharedMemorySize,
                         ATT_SMEM);
    cudaFuncSetAttribute(gemm_mma_impl<0>, cudaFuncAttributeMaxDynamicSharedMemorySize,
                         GEMM_SMEM);
    cudaFuncSetAttribute(gemm_mma_impl<1>, cudaFuncAttributeMaxDynamicSharedMemorySize,
                         GEMM_SMEM);

    __half *Xh, *Xl, *Wq, *Ath, *Atl, *Wo;
    cudaGetSymbolAddress((void**)&Xh,  g_Xh);
    cudaGetSymbolAddress((void**)&Xl,  g_Xl);
    cudaGetSymbolAddress((void**)&Wq,  g_Wq);
    cudaGetSymbolAddress((void**)&Ath, g_Ath);
    cudaGetSymbolAddress((void**)&Atl, g_Atl);
    cudaGetSymbolAddress((void**)&Wo,  g_Wo);

    // launch order fixed so ncu (-s 5 -c 1) captures attn_mma
    build_mask_kernel<<<1, NBQ>>>(mask);                                  // 0
    split6_kernel<<<dim3(PLANE4 / 256, 6), 256>>>(                        // 1
        (const float4*)xin[0], (const float4*)xin[1], (const float4*)xin[2],
        (const float4*)xin[3], (const float4*)xin[4], (const float4*)xin[5],
        (uint2*)Xh, (uint2*)Xl);
    cvt_kernel<<<(768 * 768 / 4 + 255) / 256, 256>>>((const float4*)W_qkv,
        (uint2*)Wq, 768 * 768 / 4);                                       // 2
    cvt_kernel<<<(256 * 256 / 4 + 255) / 256, 256>>>((const float4*)W_out,
        (uint2*)Wo, 256 * 256 / 4);                                       // 3
    gemm_mma_impl<0><<<dim3(6, MTOT / 128), 256, GEMM_SMEM>>>(            // 4
        Xh, Xl, Wq, b_qkv, nullptr);
    attn_mma<<<dim3(NBQ, 2, BQ), 128, ATT_SMEM>>>();                      // 5 <- ncu
    gemm_mma_impl<1><<<dim3(2, MTOT / 128), 256, GEMM_SMEM>>>(            // 6
        Ath, Atl, Wo, b_out, out);
}

// round 9
// speedup vs baseline: 1.6994x; 1.1847x over previous
#include <cuda_runtime.h>
#include <cuda_fp16.h>
#include <math_constants.h>
#include <cstdint>

// Problem constants
#define BQ   4
#define LQ   4096
#define DQ   128
#define NBQ  64
#define MTOT (BQ * LQ)     // 16384 rows

// ---------------------------------------------------------------------------
// Scratch (__device__ globals; no allocations allowed)
// A-side operands fp16 hi/lo (exact to ~2^-22); B-side single fp16.
// ---------------------------------------------------------------------------
__device__ __half g_Wq[768 * 768];           // W_qkv, single fp16 (B operand)
__device__ __half g_QKVh[6 * MTOT * DQ];     // Q planes: hi; K/V planes: single
__device__ __half g_QKVl[6 * MTOT * DQ];     // Q planes: lo (K/V region unused)
__device__ __half g_Ath[MTOT * 256];         // attention out hi/lo (A operand)
__device__ __half g_Atl[MTOT * 256];
__device__ __half g_Wo[256 * 256];           // W_out, single fp16
__device__ int g_cnt[NBQ];
__device__ int g_list[NBQ][NBQ];

// ---------------------------------------------------------------------------
// Helpers
// ---------------------------------------------------------------------------
__device__ __forceinline__ uint32_t smem_to_u32(const void* p) {
    uint32_t a;
    asm("{ .reg .u64 t; cvta.to.shared.u64 t, %1; cvt.u32.u64 %0, t; }" : "=r"(a) : "l"(p));
    return a;
}
__device__ __forceinline__ void cp16(uint32_t dst_smem, const void* src) {
    asm volatile("cp.async.cg.shared.global [%0], [%1], 16;" :: "r"(dst_smem), "l"(src));
}
#define CP_COMMIT() asm volatile("cp.async.commit_group;" ::: "memory")
#define CP_WAIT(n)  asm volatile("cp.async.wait_group %0;" :: "n"(n) : "memory")

__device__ __forceinline__ void ldmx4(uint32_t* r, uint32_t addr) {
    asm volatile("ldmatrix.sync.aligned.m8n8.x4.shared.b16 {%0,%1,%2,%3}, [%4];"
                 : "=r"(r[0]), "=r"(r[1]), "=r"(r[2]), "=r"(r[3]) : "r"(addr));
}
__device__ __forceinline__ void ldmx4t(uint32_t* r, uint32_t addr) {
    asm volatile("ldmatrix.sync.aligned.m8n8.x4.trans.shared.b16 {%0,%1,%2,%3}, [%4];"
                 : "=r"(r[0]), "=r"(r[1]), "=r"(r[2]), "=r"(r[3]) : "r"(addr));
}
__device__ __forceinline__ void ldmx2(uint32_t* r, uint32_t addr) {
    asm volatile("ldmatrix.sync.aligned.m8n8.x2.shared.b16 {%0,%1}, [%2];"
                 : "=r"(r[0]), "=r"(r[1]) : "r"(addr));
}
__device__ __forceinline__ void mma_fp16(float* c, const uint32_t* a,
                                         uint32_t b0, uint32_t b1) {
    asm volatile(
        "mma.sync.aligned.m16n8k16.row.col.f32.f16.f16.f32 "
        "{%0,%1,%2,%3}, {%4,%5,%6,%7}, {%8,%9}, {%0,%1,%2,%3};"
        : "+f"(c[0]), "+f"(c[1]), "+f"(c[2]), "+f"(c[3])
        : "r"(a[0]), "r"(a[1]), "r"(a[2]), "r"(a[3]), "r"(b0), "r"(b1));
}
__device__ __forceinline__ uint32_t pack_h2(float a, float b) {
    __half2 t = __floats2half2_rn(a, b);
    return *(uint32_t*)&t;
}
__device__ __forceinline__ void split2h(float a, float b, uint32_t& h, uint32_t& l) {
    __half ha = __float2half_rn(a);
    __half hb = __float2half_rn(b);
    h = ((uint32_t)__half_as_ushort(hb) << 16) | __half_as_ushort(ha);
    l = pack_h2(a - __half2float(ha), b - __half2float(hb));
}

// ---------------------------------------------------------------------------
// Block-mask compaction (per-qblock lists)
// ---------------------------------------------------------------------------
__global__ void build_mask_kernel(const void* __restrict__ mask)
{
    int qb = threadIdx.x;
    if (qb >= NBQ) return;
    const float* mf = (const float*)mask;
    const int*   mi = (const int*)mask;
    const unsigned char* mb = (const unsigned char*)mask;
    int mode;
    if (mf[0] == 1.0f)   mode = 0;
    else if (mi[0] == 1) mode = 1;
    else                 mode = 2;
    int cnt = 0;
    for (int kb = 0; kb <= qb; kb++) {
        size_t idx = (size_t)(qb * 64) * (size_t)LQ + (size_t)(kb * 64);
        bool on;
        if (mode == 0)      on = (mf[idx] != 0.0f);
        else if (mode == 1) on = (mi[idx] != 0);
        else                on = (mb[idx] != 0);
        if (on) g_list[qb][cnt++] = kb;
    }
    g_cnt[qb] = cnt;
}

// fp32 -> single fp16 (weights, B operand)
__global__ void cvt_kernel(const float4* __restrict__ src,
                           uint2* __restrict__ dst, int n4)
{
    int i = blockIdx.x * 256 + threadIdx.x;
    if (i >= n4) return;
    float4 v = src[i];
    dst[i] = make_uint2(pack_h2(v.x, v.y), pack_h2(v.z, v.w));
}

// ---------------------------------------------------------------------------
// Shared GEMM geometry: tile 128(M) x 256(N) x 32(K), 8 warps (2M x 4N),
// each warp 64x64 (acc[4][8][4]). smem rows stride 40 fp16 (80B).
// ---------------------------------------------------------------------------
#define GSTRIDE 40
#define A_MATB  (128 * GSTRIDE * 2)     // 10240 B per A matrix tile
#define B_MATB  (256 * GSTRIDE * 2)     // 20480 B per B matrix tile
#define STAGEB  (2 * A_MATB + B_MATB)   // Ah, Al, B = 40960
#define GEMM_SMEM (2 * STAGEB)          // 81920

// ---------------------------------------------------------------------------
// QKV GEMM: Y[16384,768] = X @ Wq^T + b. A = X fp32 (6 planes), converted to
// fp16 hi/lo IN THE LOADER (register-pipelined) — no separate split pass.
// 2-term fp16: D = Ah@B + Al@B. Output planes 0,1 (Q) -> hi/lo; 2..5 single.
// Grid (3, 128).
// ---------------------------------------------------------------------------
__global__ __launch_bounds__(256, 1) void gemm_qkv(
    const float* __restrict__ x0, const float* __restrict__ x1,
    const float* __restrict__ x2, const float* __restrict__ x3,
    const float* __restrict__ x4, const float* __restrict__ x5,
    const __half* __restrict__ W, const float* __restrict__ bias)
{
    constexpr int NCH = 24;   // 768 / 32

    extern __shared__ __align__(128) char smc[];
    uint32_t sbase0 = smem_to_u32(smc);

    int tid  = threadIdx.x;
    int warp = tid >> 5, lane = tid & 31;
    int wm = warp & 1;
    int wn = warp >> 1;
    int m0 = blockIdx.y * 128;
    int n0 = blockIdx.x * 256;

    float4 pre[4];   // A prefetch: 2 groups x 8 fp32 per thread

    auto ldA = [&](int ch) {
        int k0 = ch * 32;
        int pl = k0 >> 7, kc = k0 & 127;
        const float* xp = (pl == 0) ? x0 : (pl == 1) ? x1 : (pl == 2) ? x2
                        : (pl == 3) ? x3 : (pl == 4) ? x4 : x5;
#pragma unroll
        for (int i = 0; i < 2; i++) {
            int e = tid + i * 256;
            int r = e >> 2, seg = e & 3;
            const float* s = xp + (size_t)(m0 + r) * 128 + kc + seg * 8;
            pre[2 * i]     = *(const float4*)s;
            pre[2 * i + 1] = *(const float4*)(s + 4);
        }
    };
    auto stsA = [&](int buf) {
        char* base = smc + buf * STAGEB;
#pragma unroll
        for (int i = 0; i < 2; i++) {
            int e = tid + i * 256;
            int r = e >> 2, seg = e & 3;
            float4 v0 = pre[2 * i], v1 = pre[2 * i + 1];
            uint32_t h[4], l[4];
            split2h(v0.x, v0.y, h[0], l[0]);
            split2h(v0.z, v0.w, h[1], l[1]);
            split2h(v1.x, v1.y, h[2], l[2]);
            split2h(v1.z, v1.w, h[3], l[3]);
            uint32_t off = (uint32_t)(r * GSTRIDE + seg * 8) * 2;    // 16B-aligned
            *(uint4*)(base + off)          = make_uint4(h[0], h[1], h[2], h[3]);
            *(uint4*)(base + A_MATB + off) = make_uint4(l[0], l[1], l[2], l[3]);
        }
    };
    auto ldB = [&](int ch, int buf) {
        int k0 = ch * 32;
        uint32_t sbB = sbase0 + buf * STAGEB + 2 * A_MATB;
#pragma unroll
        for (int i = 0; i < 4; i++) {
            int e = tid + i * 256;           // 0..1023 = 256 rows x 4 chunks
            int r = e >> 2, seg = e & 3;
            size_t gb = (size_t)(n0 + r) * 768 + k0 + seg * 8;
            cp16(sbB + (uint32_t)(r * GSTRIDE + seg * 8) * 2, W + gb);
        }
    };

    float acc[4][8][4];
#pragma unroll
    for (int mf = 0; mf < 4; mf++)
#pragma unroll
        for (int nf = 0; nf < 8; nf++)
#pragma unroll
            for (int j = 0; j < 4; j++) acc[mf][nf][j] = 0.f;

    ldA(0); stsA(0); ldB(0, 0); CP_COMMIT();
    ldA(1); stsA(1); ldB(1, 1); CP_COMMIT();
    CP_WAIT(1);
    __syncthreads();

    int li = lane & 15;
    uint32_t a_row_off = (uint32_t)((wm * 64 + li) * GSTRIDE) * 2;
    uint32_t a_col_off = (uint32_t)((lane >> 4) * 8) * 2;
    uint32_t b_row_off = (uint32_t)(2 * A_MATB) + (uint32_t)((wn * 64 + (li & 7)) * GSTRIDE) * 2;
    uint32_t b_col_off = (uint32_t)((li >> 3) * 8) * 2;

    for (int ch = 0; ch < NCH; ch++) {
        uint32_t sb = sbase0 + (ch & 1) * STAGEB;
        if (ch + 2 < NCH) ldA(ch + 2);       // LDG early; latency hidden by MMAs
#pragma unroll
        for (int k16 = 0; k16 < 2; k16++) {
            uint32_t kofs = (uint32_t)(k16 * 16) * 2;
            uint32_t ah[4][4], al[4][4];
#pragma unroll
            for (int mf = 0; mf < 4; mf++) {
                uint32_t addr = sb + a_row_off
                              + (uint32_t)(mf * 16 * GSTRIDE * 2) + kofs + a_col_off;
                ldmx4(ah[mf], addr);
                ldmx4(al[mf], addr + A_MATB);
            }
            uint32_t bb[8][2];
#pragma unroll
            for (int nf = 0; nf < 8; nf++) {
                uint32_t addr = sb + b_row_off
                              + (uint32_t)(nf * 8 * GSTRIDE * 2) + kofs + b_col_off;
                ldmx2(bb[nf], addr);
            }
#pragma unroll
            for (int mf = 0; mf < 4; mf++)
#pragma unroll
                for (int nf = 0; nf < 8; nf++) {
                    mma_fp16(acc[mf][nf], ah[mf], bb[nf][0], bb[nf][1]);
                    mma_fp16(acc[mf][nf], al[mf], bb[nf][0], bb[nf][1]);
                }
        }
        __syncthreads();
        if (ch + 2 < NCH) { stsA(ch & 1); ldB(ch + 2, ch & 1); CP_COMMIT(); }
        if (ch + 1 < NCH) {
            if (ch + 2 < NCH) { CP_WAIT(1); } else { CP_WAIT(0); }
            __syncthreads();
        }
    }

    // epilogue: planes 0,1 (Q) -> fp16 hi/lo; planes 2..5 (K,V) -> single fp16
#pragma unroll
    for (int mf = 0; mf < 4; mf++) {
        int r0 = m0 + wm * 64 + mf * 16 + (lane >> 2);
        int r1 = r0 + 8;
#pragma unroll
        for (int nf = 0; nf < 8; nf++) {
            int cp = wn * 64 + nf * 8 + (lane & 3) * 2;
            int gcol = n0 + cp;
            float b0 = __ldg(bias + gcol);
            float b1 = __ldg(bias + gcol + 1);
            float v00 = acc[mf][nf][0] + b0, v01 = acc[mf][nf][1] + b1;
            float v10 = acc[mf][nf][2] + b0, v11 = acc[mf][nf][3] + b1;
            int plane = gcol >> 7, pcol = gcol & 127;
            size_t base = (size_t)plane * MTOT * 128;
            if (plane < 2) {
                uint32_t w0h, w0l, w1h, w1l;
                split2h(v00, v01, w0h, w0l);
                split2h(v10, v11, w1h, w1l);
                *(uint32_t*)(g_QKVh + base + (size_t)r0 * 128 + pcol) = w0h;
                *(uint32_t*)(g_QKVl + base + (size_t)r0 * 128 + pcol) = w0l;
                *(uint32_t*)(g_QKVh + base + (size_t)r1 * 128 + pcol) = w1h;
                *(uint32_t*)(g_QKVl + base + (size_t)r1 * 128 + pcol) = w1l;
            } else {
                *(uint32_t*)(g_QKVh + base + (size_t)r0 * 128 + pcol) = pack_h2(v00, v01);
                *(uint32_t*)(g_QKVh + base + (size_t)r1 * 128 + pcol) = pack_h2(v10, v11);
            }
        }
    }
}

// ---------------------------------------------------------------------------
// Output GEMM: out[16384,256] = At @ Wo^T + b. A = g_Ath/g_Atl fp16 hi/lo
// (cp.async), B = g_Wo. Tile 128x256 covers full N. Grid (1, 128).
// ---------------------------------------------------------------------------
__global__ __launch_bounds__(256, 1) void gemm_out(
    const __half* __restrict__ Ah, const __half* __restrict__ Al,
    const __half* __restrict__ B,
    const float* __restrict__ bias, float* __restrict__ Cout)
{
    constexpr int NCH = 8;    // 256 / 32

    extern __shared__ __align__(128) char smc[];
    uint32_t sbase0 = smem_to_u32(smc);

    int tid  = threadIdx.x;
    int warp = tid >> 5, lane = tid & 31;
    int wm = warp & 1;
    int wn = warp >> 1;
    int m0 = blockIdx.y * 128;

    auto load_stage = [&](int ch, int buf) {
        int k0 = ch * 32;
        uint32_t sb = sbase0 + buf * STAGEB;
#pragma unroll
        for (int i = 0; i < 2; i++) {
            int e = tid + i * 256;           // A: 128 rows x 4 chunks
            int r = e >> 2, seg = e & 3;
            uint32_t off = (uint32_t)(r * GSTRIDE + seg * 8) * 2;
            size_t ga = (size_t)(m0 + r) * 256 + k0 + seg * 8;
            cp16(sb + off,          Ah + ga);
            cp16(sb + A_MATB + off, Al + ga);
        }
#pragma unroll
        for (int i = 0; i < 4; i++) {
            int e = tid + i * 256;           // B: 256 rows x 4 chunks
            int r = e >> 2, seg = e & 3;
            size_t gb = (size_t)r * 256 + k0 + seg * 8;
            cp16(sb + 2 * A_MATB + (uint32_t)(r * GSTRIDE + seg * 8) * 2, B + gb);
        }
    };

    float acc[4][8][4];
#pragma unroll
    for (int mf = 0; mf < 4; mf++)
#pragma unroll
        for (int nf = 0; nf < 8; nf++)
#pragma unroll
            for (int j = 0; j < 4; j++) acc[mf][nf][j] = 0.f;

    load_stage(0, 0); CP_COMMIT();
    load_stage(1, 1); CP_COMMIT();
    CP_WAIT(1);
    __syncthreads();

    int li = lane & 15;
    uint32_t a_row_off = (uint32_t)((wm * 64 + li) * GSTRIDE) * 2;
    uint32_t a_col_off = (uint32_t)((lane >> 4) * 8) * 2;
    uint32_t b_row_off = (uint32_t)(2 * A_MATB) + (uint32_t)((wn * 64 + (li & 7)) * GSTRIDE) * 2;
    uint32_t b_col_off = (uint32_t)((li >> 3) * 8) * 2;

    for (int ch = 0; ch < NCH; ch++) {
        uint32_t sb = sbase0 + (ch & 1) * STAGEB;
#pragma unroll
        for (int k16 = 0; k16 < 2; k16++) {
            uint32_t kofs = (uint32_t)(k16 * 16) * 2;
            uint32_t ah[4][4], al[4][4];
#pragma unroll
            for (int mf = 0; mf < 4; mf++) {
                uint32_t addr = sb + a_row_off
                              + (uint32_t)(mf * 16 * GSTRIDE * 2) + kofs + a_col_off;
                ldmx4(ah[mf], addr);
                ldmx4(al[mf], addr + A_MATB);
            }
            uint32_t bb[8][2];
#pragma unroll
            for (int nf = 0; nf < 8; nf++) {
                uint32_t addr = sb + b_row_off
                              + (uint32_t)(nf * 8 * GSTRIDE * 2) + kofs + b_col_off;
                ldmx2(bb[nf], addr);
            }
#pragma unroll
            for (int mf = 0; mf < 4; mf++)
#pragma unroll
                for (int nf = 0; nf < 8; nf++) {
                    mma_fp16(acc[mf][nf], ah[mf], bb[nf][0], bb[nf][1]);
                    mma_fp16(acc[mf][nf], al[mf], bb[nf][0], bb[nf][1]);
                }
        }
        __syncthreads();
        if (ch + 2 < NCH) { load_stage(ch + 2, ch & 1); CP_COMMIT(); }
        if (ch + 1 < NCH) {
            if (ch + 2 < NCH) { CP_WAIT(1); } else { CP_WAIT(0); }
            __syncthreads();
        }
    }

#pragma unroll
    for (int mf = 0; mf < 4; mf++) {
        int r0 = m0 + wm * 64 + mf * 16 + (lane >> 2);
        int r1 = r0 + 8;
#pragma unroll
        for (int nf = 0; nf < 8; nf++) {
            int gcol = wn * 64 + nf * 8 + (lane & 3) * 2;
            float b0 = __ldg(bias + gcol);
            float b1 = __ldg(bias + gcol + 1);
            int half = gcol >> 7, pcol = gcol & 127;
            float* dst = Cout + (size_t)half * MTOT * 128;
            *(float2*)(dst + (size_t)r0 * 128 + pcol) =
                make_float2(acc[mf][nf][0] + b0, acc[mf][nf][1] + b1);
            *(float2*)(dst + (size_t)r1 * 128 + pcol) =
                make_float2(acc[mf][nf][2] + b0, acc[mf][nf][3] + b1);
        }
    }
}

// ---------------------------------------------------------------------------
// HMMA block-sparse flash attention, fp16 2-term (unchanged from R8).
// Grid (NBQ, 2, BQ); 128 threads; 2 CTAs/SM; double-buffered K/V.
// ---------------------------------------------------------------------------
#define AST   136
#define AMATB (64 * AST * 2)            // 17408 bytes per 64x128 matrix
#define ATT_SMEM (6 * AMATB)            // 104448

__global__ __launch_bounds__(128, 2) void attn_mma()
{
    extern __shared__ __align__(128) char sma[];
    uint32_t sb = smem_to_u32(sma);

    int tid  = threadIdx.x;
    int warp = tid >> 5, lane = tid & 31;
    int qb   = blockIdx.x;
    int part = blockIdx.y;
    int b    = blockIdx.z;

    const __half* Qh = g_QKVh + (size_t)(0 + part) * MTOT * 128;
    const __half* Ql = g_QKVl + (size_t)(0 + part) * MTOT * 128;
    const __half* Kp = g_QKVh + (size_t)(2 + part) * MTOT * 128;
    const __half* Vp = g_QKVh + (size_t)(4 + part) * MTOT * 128;

    int qrow0 = b * LQ + qb * 64;
    const float SC = 0.08838834764831845f * 1.4426950408889634f;

    auto load_q = [&]() {
#pragma unroll
        for (int i = 0; i < 16; i++) {
            int e = tid + i * 128;
            int mat = e >> 10;
            int idx = e & 1023;
            int r = idx >> 4, c = idx & 15;
            const __half* src = (mat ? Ql : Qh) + (size_t)(qrow0 + r) * 128 + c * 8;
            cp16(sb + (uint32_t)(mat * AMATB) + (uint32_t)(r * AST + c * 8) * 2, src);
        }
    };
    auto load_kv = [&](int kb, int s) {
        int krow0 = b * LQ + kb * 64;
        uint32_t stb = sb + (uint32_t)((2 + 2 * s) * AMATB);
#pragma unroll
        for (int i = 0; i < 16; i++) {
            int e = tid + i * 128;
            int mat = e >> 10;
            int idx = e & 1023;
            int r = idx >> 4, c = idx & 15;
            const __half* src = (mat ? Vp : Kp) + (size_t)(krow0 + r) * 128 + c * 8;
            cp16(stb + (uint32_t)(mat * AMATB) + (uint32_t)(r * AST + c * 8) * 2, src);
        }
    };

    float O[16][4];
#pragma unroll
    for (int nf = 0; nf < 16; nf++)
#pragma unroll
        for (int j = 0; j < 4; j++) O[nf][j] = 0.f;
    float m2_0 = -1e30f, m2_1 = -1e30f;
    float l0 = 0.f, l1 = 0.f;

    int cnt = g_cnt[qb];
    const int* list = g_list[qb];

    load_q(); load_kv(list[0], 0); CP_COMMIT();
    if (cnt > 1) { load_kv(list[1], 1); CP_COMMIT(); }
    if (cnt > 1) { CP_WAIT(1); } else { CP_WAIT(0); }
    __syncthreads();

    int li = lane & 15;
    uint32_t a_off  = (uint32_t)((warp * 16 + li) * AST + (lane >> 4) * 8) * 2;
    uint32_t kv_row = (uint32_t)(li * AST + (lane >> 4) * 8) * 2;

    for (int i = 0; i < cnt; i++) {
        int s = i & 1;
        uint32_t sK = sb + (uint32_t)((2 + 2 * s) * AMATB);
        uint32_t sV = sK + AMATB;

        float sv[8][4];
#pragma unroll
        for (int nf = 0; nf < 8; nf++)
#pragma unroll
            for (int j = 0; j < 4; j++) sv[nf][j] = 0.f;

#pragma unroll
        for (int kd = 0; kd < 8; kd++) {
            uint32_t qaddr = sb + a_off + (uint32_t)(kd * 16) * 2;
            uint32_t aH[4], aL[4];
            ldmx4(aH, qaddr);
            ldmx4(aL, qaddr + AMATB);
#pragma unroll
            for (int jg = 0; jg < 4; jg++) {
                uint32_t kaddr = sK + kv_row
                               + (uint32_t)(jg * 16 * AST + kd * 16) * 2;
                uint32_t bK[4];
                ldmx4(bK, kaddr);
                mma_fp16(sv[jg * 2],     aH, bK[0], bK[2]);
                mma_fp16(sv[jg * 2],     aL, bK[0], bK[2]);
                mma_fp16(sv[jg * 2 + 1], aH, bK[1], bK[3]);
                mma_fp16(sv[jg * 2 + 1], aL, bK[1], bK[3]);
            }
        }

        float mx0 = -1e30f, mx1 = -1e30f;
#pragma unroll
        for (int nf = 0; nf < 8; nf++) {
#pragma unroll
            for (int j = 0; j < 4; j++) sv[nf][j] *= SC;
            mx0 = fmaxf(mx0, fmaxf(sv[nf][0], sv[nf][1]));
            mx1 = fmaxf(mx1, fmaxf(sv[nf][2], sv[nf][3]));
        }
        mx0 = fmaxf(mx0, __shfl_xor_sync(0xffffffffu, mx0, 1));
        mx0 = fmaxf(mx0, __shfl_xor_sync(0xffffffffu, mx0, 2));
        mx1 = fmaxf(mx1, __shfl_xor_sync(0xffffffffu, mx1, 1));
        mx1 = fmaxf(mx1, __shfl_xor_sync(0xffffffffu, mx1, 2));

        float m0n = fmaxf(m2_0, mx0);
        float m1n = fmaxf(m2_1, mx1);
        float cor0 = exp2f(m2_0 - m0n);
        float cor1 = exp2f(m2_1 - m1n);
        m2_0 = m0n; m2_1 = m1n;

        uint32_t ph[8][2], pl[8][2];
        float ls0 = 0.f, ls1 = 0.f;
#pragma unroll
        for (int nf = 0; nf < 8; nf++) {
            float p0 = exp2f(sv[nf][0] - m0n);
            float p1 = exp2f(sv[nf][1] - m0n);
            float p2 = exp2f(sv[nf][2] - m1n);
            float p3 = exp2f(sv[nf][3] - m1n);
            ls0 += p0 + p1; ls1 += p2 + p3;
            split2h(p0, p1, ph[nf][0], pl[nf][0]);
            split2h(p2, p3, ph[nf][1], pl[nf][1]);
        }
        ls0 += __shfl_xor_sync(0xffffffffu, ls0, 1);
        ls0 += __shfl_xor_sync(0xffffffffu, ls0, 2);
        ls1 += __shfl_xor_sync(0xffffffffu, ls1, 1);
        ls1 += __shfl_xor_sync(0xffffffffu, ls1, 2);
        l0 = l0 * cor0 + ls0;
        l1 = l1 * cor1 + ls1;

#pragma unroll
        for (int nf = 0; nf < 16; nf++) {
            O[nf][0] *= cor0; O[nf][1] *= cor0;
            O[nf][2] *= cor1; O[nf][3] *= cor1;
        }

#pragma unroll
        for (int kk = 0; kk < 4; kk++) {
            uint32_t aH[4] = {ph[2*kk][0], ph[2*kk][1], ph[2*kk+1][0], ph[2*kk+1][1]};
            uint32_t aL[4] = {pl[2*kk][0], pl[2*kk][1], pl[2*kk+1][0], pl[2*kk+1][1]};
#pragma unroll
            for (int dg = 0; dg < 8; dg++) {
                uint32_t vaddr = sV + kv_row
                               + (uint32_t)(kk * 16 * AST + dg * 16) * 2;
                uint32_t vV[4];
                ldmx4t(vV, vaddr);
                mma_fp16(O[dg * 2],     aH, vV[0], vV[1]);
                mma_fp16(O[dg * 2],     aL, vV[0], vV[1]);
                mma_fp16(O[dg * 2 + 1], aH, vV[2], vV[3]);
                mma_fp16(O[dg * 2 + 1], aL, vV[2], vV[3]);
            }
        }

        __syncthreads();
        if (i + 2 < cnt) { load_kv(list[i + 2], s); CP_COMMIT(); }
        if (i + 1 < cnt) {
            if (i + 2 < cnt) { CP_WAIT(1); } else { CP_WAIT(0); }
            __syncthreads();
        }
    }

    float inv0 = 1.f / l0, inv1 = 1.f / l1;
    int r0 = qrow0 + warp * 16 + (lane >> 2);
    int r1 = r0 + 8;
#pragma unroll
    for (int nf = 0; nf < 16; nf++) {
        int col = part * 128 + nf * 8 + (lane & 3) * 2;
        uint32_t wh, wl;
        split2h(O[nf][0] * inv0, O[nf][1] * inv0, wh, wl);
        *(uint32_t*)(g_Ath + (size_t)r0 * 256 + col) = wh;
        *(uint32_t*)(g_Atl + (size_t)r0 * 256 + col) = wl;
        split2h(O[nf][2] * inv1, O[nf][3] * inv1, wh, wl);
        *(uint32_t*)(g_Ath + (size_t)r1 * 256 + col) = wh;
        *(uint32_t*)(g_Atl + (size_t)r1 * 256 + col) = wl;
    }
}

// ---------------------------------------------------------------------------
// Launch
// ---------------------------------------------------------------------------
extern "C" void kernel_launch(void* const* d_in, const int* in_sizes, int n_in,
                              void* d_out, int out_size)
{
    const float* xin[6];
    for (int i = 0; i < 6; i++) xin[i] = (const float*)d_in[i];
    const float* W_qkv  = (const float*)d_in[6];
    const float* b_qkv  = (const float*)d_in[7];
    const float* W_out  = (const float*)d_in[8];
    const float* b_out  = (const float*)d_in[9];
    const void*  mask   = d_in[10];
    float* out = (float*)d_out;
    (void)in_sizes; (void)n_in; (void)out_size;

    cudaFuncSetAttribute(attn_mma, cudaFuncAttributeMaxDynamicSharedMemorySize,
                         ATT_SMEM);
    cudaFuncSetAttribute(gemm_qkv, cudaFuncAttributeMaxDynamicSharedMemorySize,
                         GEMM_SMEM);
    cudaFuncSetAttribute(gemm_out, cudaFuncAttributeMaxDynamicSharedMemorySize,
                         GEMM_SMEM);

    __half *Wq, *Ath, *Atl, *Wo;
    cudaGetSymbolAddress((void**)&Wq,  g_Wq);
    cudaGetSymbolAddress((void**)&Ath, g_Ath);
    cudaGetSymbolAddress((void**)&Atl, g_Atl);
    cudaGetSymbolAddress((void**)&Wo,  g_Wo);

    build_mask_kernel<<<1, NBQ>>>(mask);                                  // 0
    cvt_kernel<<<(768 * 768 / 4 + 255) / 256, 256>>>((const float4*)W_qkv,
        (uint2*)Wq, 768 * 768 / 4);                                       // 1
    cvt_kernel<<<(256 * 256 / 4 + 255) / 256, 256>>>((const float4*)W_out,
        (uint2*)Wo, 256 * 256 / 4);                                       // 2
    gemm_qkv<<<dim3(3, MTOT / 128), 256, GEMM_SMEM>>>(                    // 3
        xin[0], xin[1], xin[2], xin[3], xin[4], xin[5], Wq, b_qkv);
    attn_mma<<<dim3(NBQ, 2, BQ), 128, ATT_SMEM>>>();                      // 4
    gemm_out<<<dim3(1, MTOT / 128), 256, GEMM_SMEM>>>(                    // 5 <- ncu
        Ath, Atl, Wo, b_out, out);
}

// round 10
// speedup vs baseline: 1.7020x; 1.0015x over previous
#include <cuda_runtime.h>
#include <cuda_fp16.h>
#include <math_constants.h>
#include <cstdint>

// Problem constants
#define BQ   4
#define LQ   4096
#define DQ   128
#define NBQ  64
#define MTOT (BQ * LQ)     // 16384 rows

// ---------------------------------------------------------------------------
// Scratch (__device__ globals; no allocations allowed)
// A-side operands fp16 hi/lo (exact to ~2^-22); B-side single fp16.
// ---------------------------------------------------------------------------
__device__ __half g_Wq[768 * 768];           // W_qkv, single fp16 (B operand)
__device__ __half g_QKVh[6 * MTOT * DQ];     // Q planes: hi; K/V planes: single
__device__ __half g_QKVl[6 * MTOT * DQ];     // Q planes: lo (K/V region unused)
__device__ __half g_Ath[MTOT * 256];         // attention out hi/lo (A operand)
__device__ __half g_Atl[MTOT * 256];
__device__ __half g_Wo[256 * 256];           // W_out, single fp16
__device__ int g_cnt[NBQ];
__device__ int g_list[NBQ][NBQ];

// ---------------------------------------------------------------------------
// Helpers
// ---------------------------------------------------------------------------
__device__ __forceinline__ uint32_t smem_to_u32(const void* p) {
    uint32_t a;
    asm("{ .reg .u64 t; cvta.to.shared.u64 t, %1; cvt.u32.u64 %0, t; }" : "=r"(a) : "l"(p));
    return a;
}
__device__ __forceinline__ void cp16(uint32_t dst_smem, const void* src) {
    asm volatile("cp.async.cg.shared.global [%0], [%1], 16;" :: "r"(dst_smem), "l"(src));
}
#define CP_COMMIT() asm volatile("cp.async.commit_group;" ::: "memory")
#define CP_WAIT(n)  asm volatile("cp.async.wait_group %0;" :: "n"(n) : "memory")

__device__ __forceinline__ void ldmx4(uint32_t* r, uint32_t addr) {
    asm volatile("ldmatrix.sync.aligned.m8n8.x4.shared.b16 {%0,%1,%2,%3}, [%4];"
                 : "=r"(r[0]), "=r"(r[1]), "=r"(r[2]), "=r"(r[3]) : "r"(addr));
}
__device__ __forceinline__ void ldmx4t(uint32_t* r, uint32_t addr) {
    asm volatile("ldmatrix.sync.aligned.m8n8.x4.trans.shared.b16 {%0,%1,%2,%3}, [%4];"
                 : "=r"(r[0]), "=r"(r[1]), "=r"(r[2]), "=r"(r[3]) : "r"(addr));
}
__device__ __forceinline__ void ldmx2(uint32_t* r, uint32_t addr) {
    asm volatile("ldmatrix.sync.aligned.m8n8.x2.shared.b16 {%0,%1}, [%2];"
                 : "=r"(r[0]), "=r"(r[1]) : "r"(addr));
}
__device__ __forceinline__ void mma_fp16(float* c, const uint32_t* a,
                                         uint32_t b0, uint32_t b1) {
    asm volatile(
        "mma.sync.aligned.m16n8k16.row.col.f32.f16.f16.f32 "
        "{%0,%1,%2,%3}, {%4,%5,%6,%7}, {%8,%9}, {%0,%1,%2,%3};"
        : "+f"(c[0]), "+f"(c[1]), "+f"(c[2]), "+f"(c[3])
        : "r"(a[0]), "r"(a[1]), "r"(a[2]), "r"(a[3]), "r"(b0), "r"(b1));
}
__device__ __forceinline__ uint32_t pack_h2(float a, float b) {
    __half2 t = __floats2half2_rn(a, b);
    return *(uint32_t*)&t;
}
__device__ __forceinline__ void split2h(float a, float b, uint32_t& h, uint32_t& l) {
    __half ha = __float2half_rn(a);
    __half hb = __float2half_rn(b);
    h = ((uint32_t)__half_as_ushort(hb) << 16) | __half_as_ushort(ha);
    l = pack_h2(a - __half2float(ha), b - __half2float(hb));
}

// ---------------------------------------------------------------------------
// Block-mask compaction (per-qblock lists)
// ---------------------------------------------------------------------------
__global__ void build_mask_kernel(const void* __restrict__ mask)
{
    int qb = threadIdx.x;
    if (qb >= NBQ) return;
    const float* mf = (const float*)mask;
    const int*   mi = (const int*)mask;
    const unsigned char* mb = (const unsigned char*)mask;
    int mode;
    if (mf[0] == 1.0f)   mode = 0;
    else if (mi[0] == 1) mode = 1;
    else                 mode = 2;
    int cnt = 0;
    for (int kb = 0; kb <= qb; kb++) {
        size_t idx = (size_t)(qb * 64) * (size_t)LQ + (size_t)(kb * 64);
        bool on;
        if (mode == 0)      on = (mf[idx] != 0.0f);
        else if (mode == 1) on = (mi[idx] != 0);
        else                on = (mb[idx] != 0);
        if (on) g_list[qb][cnt++] = kb;
    }
    g_cnt[qb] = cnt;
}

// fp32 -> single fp16 (weights, B operand)
__global__ void cvt_kernel(const float4* __restrict__ src,
                           uint2* __restrict__ dst, int n4)
{
    int i = blockIdx.x * 256 + threadIdx.x;
    if (i >= n4) return;
    float4 v = src[i];
    dst[i] = make_uint2(pack_h2(v.x, v.y), pack_h2(v.z, v.w));
}

// ---------------------------------------------------------------------------
// Shared GEMM geometry: tile 128(M) x 256(N) x 32(K), 8 warps (2M x 4N),
// each warp 64x64 (acc[4][8][4]). smem rows stride 40 fp16 (80B).
// ---------------------------------------------------------------------------
#define GSTRIDE 40
#define A_MATB  (128 * GSTRIDE * 2)     // 10240 B per A matrix tile
#define B_MATB  (256 * GSTRIDE * 2)     // 20480 B per B matrix tile
#define STAGEB  (2 * A_MATB + B_MATB)   // Ah, Al, B = 40960
#define GEMM_SMEM (2 * STAGEB)          // 81920

// ---------------------------------------------------------------------------
// QKV GEMM: Y[16384,768] = X @ Wq^T + b. A = X fp32 (6 planes), converted to
// fp16 hi/lo IN THE LOADER (register-pipelined) — no separate split pass.
// 2-term fp16: D = Ah@B + Al@B. Output planes 0,1 (Q) -> hi/lo; 2..5 single.
// Grid (3, 128).
// ---------------------------------------------------------------------------
__global__ __launch_bounds__(256, 1) void gemm_qkv(
    const float* __restrict__ x0, const float* __restrict__ x1,
    const float* __restrict__ x2, const float* __restrict__ x3,
    const float* __restrict__ x4, const float* __restrict__ x5,
    const __half* __restrict__ W, const float* __restrict__ bias)
{
    constexpr int NCH = 24;   // 768 / 32

    extern __shared__ __align__(128) char smc[];
    uint32_t sbase0 = smem_to_u32(smc);

    int tid  = threadIdx.x;
    int warp = tid >> 5, lane = tid & 31;
    int wm = warp & 1;
    int wn = warp >> 1;
    int m0 = blockIdx.y * 128;
    int n0 = blockIdx.x * 256;

    float4 pre[4];   // A prefetch: 2 groups x 8 fp32 per thread

    auto ldA = [&](int ch) {
        int k0 = ch * 32;
        int pl = k0 >> 7, kc = k0 & 127;
        const float* xp = (pl == 0) ? x0 : (pl == 1) ? x1 : (pl == 2) ? x2
                        : (pl == 3) ? x3 : (pl == 4) ? x4 : x5;
#pragma unroll
        for (int i = 0; i < 2; i++) {
            int e = tid + i * 256;
            int r = e >> 2, seg = e & 3;
            const float* s = xp + (size_t)(m0 + r) * 128 + kc + seg * 8;
            pre[2 * i]     = *(const float4*)s;
            pre[2 * i + 1] = *(const float4*)(s + 4);
        }
    };
    auto stsA = [&](int buf) {
        char* base = smc + buf * STAGEB;
#pragma unroll
        for (int i = 0; i < 2; i++) {
            int e = tid + i * 256;
            int r = e >> 2, seg = e & 3;
            float4 v0 = pre[2 * i], v1 = pre[2 * i + 1];
            uint32_t h[4], l[4];
            split2h(v0.x, v0.y, h[0], l[0]);
            split2h(v0.z, v0.w, h[1], l[1]);
            split2h(v1.x, v1.y, h[2], l[2]);
            split2h(v1.z, v1.w, h[3], l[3]);
            uint32_t off = (uint32_t)(r * GSTRIDE + seg * 8) * 2;    // 16B-aligned
            *(uint4*)(base + off)          = make_uint4(h[0], h[1], h[2], h[3]);
            *(uint4*)(base + A_MATB + off) = make_uint4(l[0], l[1], l[2], l[3]);
        }
    };
    auto ldB = [&](int ch, int buf) {
        int k0 = ch * 32;
        uint32_t sbB = sbase0 + buf * STAGEB + 2 * A_MATB;
#pragma unroll
        for (int i = 0; i < 4; i++) {
            int e = tid + i * 256;           // 0..1023 = 256 rows x 4 chunks
            int r = e >> 2, seg = e & 3;
            size_t gb = (size_t)(n0 + r) * 768 + k0 + seg * 8;
            cp16(sbB + (uint32_t)(r * GSTRIDE + seg * 8) * 2, W + gb);
        }
    };

    float acc[4][8][4];
#pragma unroll
    for (int mf = 0; mf < 4; mf++)
#pragma unroll
        for (int nf = 0; nf < 8; nf++)
#pragma unroll
            for (int j = 0; j < 4; j++) acc[mf][nf][j] = 0.f;

    ldA(0); stsA(0); ldB(0, 0); CP_COMMIT();
    ldA(1); stsA(1); ldB(1, 1); CP_COMMIT();
    CP_WAIT(1);
    __syncthreads();

    int li = lane & 15;
    uint32_t a_row_off = (uint32_t)((wm * 64 + li) * GSTRIDE) * 2;
    uint32_t a_col_off = (uint32_t)((lane >> 4) * 8) * 2;
    uint32_t b_row_off = (uint32_t)(2 * A_MATB) + (uint32_t)((wn * 64 + (li & 7)) * GSTRIDE) * 2;
    uint32_t b_col_off = (uint32_t)((li >> 3) * 8) * 2;

    for (int ch = 0; ch < NCH; ch++) {
        uint32_t sb = sbase0 + (ch & 1) * STAGEB;
        if (ch + 2 < NCH) ldA(ch + 2);       // LDG early; latency hidden by MMAs
#pragma unroll
        for (int k16 = 0; k16 < 2; k16++) {
            uint32_t kofs = (uint32_t)(k16 * 16) * 2;
            uint32_t ah[4][4], al[4][4];
#pragma unroll
            for (int mf = 0; mf < 4; mf++) {
                uint32_t addr = sb + a_row_off
                              + (uint32_t)(mf * 16 * GSTRIDE * 2) + kofs + a_col_off;
                ldmx4(ah[mf], addr);
                ldmx4(al[mf], addr + A_MATB);
            }
            uint32_t bb[8][2];
#pragma unroll
            for (int nf = 0; nf < 8; nf++) {
                uint32_t addr = sb + b_row_off
                              + (uint32_t)(nf * 8 * GSTRIDE * 2) + kofs + b_col_off;
                ldmx2(bb[nf], addr);
            }
#pragma unroll
            for (int mf = 0; mf < 4; mf++)
#pragma unroll
                for (int nf = 0; nf < 8; nf++) {
                    mma_fp16(acc[mf][nf], ah[mf], bb[nf][0], bb[nf][1]);
                    mma_fp16(acc[mf][nf], al[mf], bb[nf][0], bb[nf][1]);
                }
        }
        __syncthreads();
        if (ch + 2 < NCH) { stsA(ch & 1); ldB(ch + 2, ch & 1); CP_COMMIT(); }
        if (ch + 1 < NCH) {
            if (ch + 2 < NCH) { CP_WAIT(1); } else { CP_WAIT(0); }
            __syncthreads();
        }
    }

    // epilogue: planes 0,1 (Q) -> fp16 hi/lo; planes 2..5 (K,V) -> single fp16
#pragma unroll
    for (int mf = 0; mf < 4; mf++) {
        int r0 = m0 + wm * 64 + mf * 16 + (lane >> 2);
        int r1 = r0 + 8;
#pragma unroll
        for (int nf = 0; nf < 8; nf++) {
            int cp = wn * 64 + nf * 8 + (lane & 3) * 2;
            int gcol = n0 + cp;
            float b0 = __ldg(bias + gcol);
            float b1 = __ldg(bias + gcol + 1);
            float v00 = acc[mf][nf][0] + b0, v01 = acc[mf][nf][1] + b1;
            float v10 = acc[mf][nf][2] + b0, v11 = acc[mf][nf][3] + b1;
            int plane = gcol >> 7, pcol = gcol & 127;
            size_t base = (size_t)plane * MTOT * 128;
            if (plane < 2) {
                uint32_t w0h, w0l, w1h, w1l;
                split2h(v00, v01, w0h, w0l);
                split2h(v10, v11, w1h, w1l);
                *(uint32_t*)(g_QKVh + base + (size_t)r0 * 128 + pcol) = w0h;
                *(uint32_t*)(g_QKVl + base + (size_t)r0 * 128 + pcol) = w0l;
                *(uint32_t*)(g_QKVh + base + (size_t)r1 * 128 + pcol) = w1h;
                *(uint32_t*)(g_QKVl + base + (size_t)r1 * 128 + pcol) = w1l;
            } else {
                *(uint32_t*)(g_QKVh + base + (size_t)r0 * 128 + pcol) = pack_h2(v00, v01);
                *(uint32_t*)(g_QKVh + base + (size_t)r1 * 128 + pcol) = pack_h2(v10, v11);
            }
        }
    }
}

// ---------------------------------------------------------------------------
// Output GEMM: out[16384,256] = At @ Wo^T + b. A = g_Ath/g_Atl fp16 hi/lo
// (cp.async), B = g_Wo. Tile 128x256 covers full N. Grid (1, 128).
// ---------------------------------------------------------------------------
__global__ __launch_bounds__(256, 1) void gemm_out(
    const __half* __restrict__ Ah, const __half* __restrict__ Al,
    const __half* __restrict__ B,
    const float* __restrict__ bias, float* __restrict__ Cout)
{
    constexpr int NCH = 8;    // 256 / 32

    extern __shared__ __align__(128) char smc[];
    uint32_t sbase0 = smem_to_u32(smc);

    int tid  = threadIdx.x;
    int warp = tid >> 5, lane = tid & 31;
    int wm = warp & 1;
    int wn = warp >> 1;
    int m0 = blockIdx.y * 128;

    auto load_stage = [&](int ch, int buf) {
        int k0 = ch * 32;
        uint32_t sb = sbase0 + buf * STAGEB;
#pragma unroll
        for (int i = 0; i < 2; i++) {
            int e = tid + i * 256;           // A: 128 rows x 4 chunks
            int r = e >> 2, seg = e & 3;
            uint32_t off = (uint32_t)(r * GSTRIDE + seg * 8) * 2;
            size_t ga = (size_t)(m0 + r) * 256 + k0 + seg * 8;
            cp16(sb + off,          Ah + ga);
            cp16(sb + A_MATB + off, Al + ga);
        }
#pragma unroll
        for (int i = 0; i < 4; i++) {
            int e = tid + i * 256;           // B: 256 rows x 4 chunks
            int r = e >> 2, seg = e & 3;
            size_t gb = (size_t)r * 256 + k0 + seg * 8;
            cp16(sb + 2 * A_MATB + (uint32_t)(r * GSTRIDE + seg * 8) * 2, B + gb);
        }
    };

    float acc[4][8][4];
#pragma unroll
    for (int mf = 0; mf < 4; mf++)
#pragma unroll
        for (int nf = 0; nf < 8; nf++)
#pragma unroll
            for (int j = 0; j < 4; j++) acc[mf][nf][j] = 0.f;

    load_stage(0, 0); CP_COMMIT();
    load_stage(1, 1); CP_COMMIT();
    CP_WAIT(1);
    __syncthreads();

    int li = lane & 15;
    uint32_t a_row_off = (uint32_t)((wm * 64 + li) * GSTRIDE) * 2;
    uint32_t a_col_off = (uint32_t)((lane >> 4) * 8) * 2;
    uint32_t b_row_off = (uint32_t)(2 * A_MATB) + (uint32_t)((wn * 64 + (li & 7)) * GSTRIDE) * 2;
    uint32_t b_col_off = (uint32_t)((li >> 3) * 8) * 2;

    for (int ch = 0; ch < NCH; ch++) {
        uint32_t sb = sbase0 + (ch & 1) * STAGEB;
#pragma unroll
        for (int k16 = 0; k16 < 2; k16++) {
            uint32_t kofs = (uint32_t)(k16 * 16) * 2;
            uint32_t ah[4][4], al[4][4];
#pragma unroll
            for (int mf = 0; mf < 4; mf++) {
                uint32_t addr = sb + a_row_off
                              + (uint32_t)(mf * 16 * GSTRIDE * 2) + kofs + a_col_off;
                ldmx4(ah[mf], addr);
                ldmx4(al[mf], addr + A_MATB);
            }
            uint32_t bb[8][2];
#pragma unroll
            for (int nf = 0; nf < 8; nf++) {
                uint32_t addr = sb + b_row_off
                              + (uint32_t)(nf * 8 * GSTRIDE * 2) + kofs + b_col_off;
                ldmx2(bb[nf], addr);
            }
#pragma unroll
            for (int mf = 0; mf < 4; mf++)
#pragma unroll
                for (int nf = 0; nf < 8; nf++) {
                    mma_fp16(acc[mf][nf], ah[mf], bb[nf][0], bb[nf][1]);
                    mma_fp16(acc[mf][nf], al[mf], bb[nf][0], bb[nf][1]);
                }
        }
        __syncthreads();
        if (ch + 2 < NCH) { load_stage(ch + 2, ch & 1); CP_COMMIT(); }
        if (ch + 1 < NCH) {
            if (ch + 2 < NCH) { CP_WAIT(1); } else { CP_WAIT(0); }
            __syncthreads();
        }
    }

#pragma unroll
    for (int mf = 0; mf < 4; mf++) {
        int r0 = m0 + wm * 64 + mf * 16 + (lane >> 2);
        int r1 = r0 + 8;
#pragma unroll
        for (int nf = 0; nf < 8; nf++) {
            int gcol = wn * 64 + nf * 8 + (lane & 3) * 2;
            float b0 = __ldg(bias + gcol);
            float b1 = __ldg(bias + gcol + 1);
            int half = gcol >> 7, pcol = gcol & 127;
            float* dst = Cout + (size_t)half * MTOT * 128;
            *(float2*)(dst + (size_t)r0 * 128 + pcol) =
                make_float2(acc[mf][nf][0] + b0, acc[mf][nf][1] + b1);
            *(float2*)(dst + (size_t)r1 * 128 + pcol) =
                make_float2(acc[mf][nf][2] + b0, acc[mf][nf][3] + b1);
        }
    }
}

// ---------------------------------------------------------------------------
// HMMA block-sparse flash attention, fp16 2-term (unchanged from R8).
// Grid (NBQ, 2, BQ); 128 threads; 2 CTAs/SM; double-buffered K/V.
// ---------------------------------------------------------------------------
#define AST   136
#define AMATB (64 * AST * 2)            // 17408 bytes per 64x128 matrix
#define ATT_SMEM (6 * AMATB)            // 104448

__global__ __launch_bounds__(128, 2) void attn_mma()
{
    extern __shared__ __align__(128) char sma[];
    uint32_t sb = smem_to_u32(sma);

    int tid  = threadIdx.x;
    int warp = tid >> 5, lane = tid & 31;
    int qb   = blockIdx.x;
    int part = blockIdx.y;
    int b    = blockIdx.z;

    const __half* Qh = g_QKVh + (size_t)(0 + part) * MTOT * 128;
    const __half* Ql = g_QKVl + (size_t)(0 + part) * MTOT * 128;
    const __half* Kp = g_QKVh + (size_t)(2 + part) * MTOT * 128;
    const __half* Vp = g_QKVh + (size_t)(4 + part) * MTOT * 128;

    int qrow0 = b * LQ + qb * 64;
    const float SC = 0.08838834764831845f * 1.4426950408889634f;

    auto load_q = [&]() {
#pragma unroll
        for (int i = 0; i < 16; i++) {
            int e = tid + i * 128;
            int mat = e >> 10;
            int idx = e & 1023;
            int r = idx >> 4, c = idx & 15;
            const __half* src = (mat ? Ql : Qh) + (size_t)(qrow0 + r) * 128 + c * 8;
            cp16(sb + (uint32_t)(mat * AMATB) + (uint32_t)(r * AST + c * 8) * 2, src);
        }
    };
    auto load_kv = [&](int kb, int s) {
        int krow0 = b * LQ + kb * 64;
        uint32_t stb = sb + (uint32_t)((2 + 2 * s) * AMATB);
#pragma unroll
        for (int i = 0; i < 16; i++) {
            int e = tid + i * 128;
            int mat = e >> 10;
            int idx = e & 1023;
            int r = idx >> 4, c = idx & 15;
            const __half* src = (mat ? Vp : Kp) + (size_t)(krow0 + r) * 128 + c * 8;
            cp16(stb + (uint32_t)(mat * AMATB) + (uint32_t)(r * AST + c * 8) * 2, src);
        }
    };

    float O[16][4];
#pragma unroll
    for (int nf = 0; nf < 16; nf++)
#pragma unroll
        for (int j = 0; j < 4; j++) O[nf][j] = 0.f;
    float m2_0 = -1e30f, m2_1 = -1e30f;
    float l0 = 0.f, l1 = 0.f;

    int cnt = g_cnt[qb];
    const int* list = g_list[qb];

    load_q(); load_kv(list[0], 0); CP_COMMIT();
    if (cnt > 1) { load_kv(list[1], 1); CP_COMMIT(); }
    if (cnt > 1) { CP_WAIT(1); } else { CP_WAIT(0); }
    __syncthreads();

    int li = lane & 15;
    uint32_t a_off  = (uint32_t)((warp * 16 + li) * AST + (lane >> 4) * 8) * 2;
    uint32_t kv_row = (uint32_t)(li * AST + (lane >> 4) * 8) * 2;

    for (int i = 0; i < cnt; i++) {
        int s = i & 1;
        uint32_t sK = sb + (uint32_t)((2 + 2 * s) * AMATB);
        uint32_t sV = sK + AMATB;

        float sv[8][4];
#pragma unroll
        for (int nf = 0; nf < 8; nf++)
#pragma unroll
            for (int j = 0; j < 4; j++) sv[nf][j] = 0.f;

#pragma unroll
        for (int kd = 0; kd < 8; kd++) {
            uint32_t qaddr = sb + a_off + (uint32_t)(kd * 16) * 2;
            uint32_t aH[4], aL[4];
            ldmx4(aH, qaddr);
            ldmx4(aL, qaddr + AMATB);
#pragma unroll
            for (int jg = 0; jg < 4; jg++) {
                uint32_t kaddr = sK + kv_row
                               + (uint32_t)(jg * 16 * AST + kd * 16) * 2;
                uint32_t bK[4];
                ldmx4(bK, kaddr);
                mma_fp16(sv[jg * 2],     aH, bK[0], bK[2]);
                mma_fp16(sv[jg * 2],     aL, bK[0], bK[2]);
                mma_fp16(sv[jg * 2 + 1], aH, bK[1], bK[3]);
                mma_fp16(sv[jg * 2 + 1], aL, bK[1], bK[3]);
            }
        }

        float mx0 = -1e30f, mx1 = -1e30f;
#pragma unroll
        for (int nf = 0; nf < 8; nf++) {
#pragma unroll
            for (int j = 0; j < 4; j++) sv[nf][j] *= SC;
            mx0 = fmaxf(mx0, fmaxf(sv[nf][0], sv[nf][1]));
            mx1 = fmaxf(mx1, fmaxf(sv[nf][2], sv[nf][3]));
        }
        mx0 = fmaxf(mx0, __shfl_xor_sync(0xffffffffu, mx0, 1));
        mx0 = fmaxf(mx0, __shfl_xor_sync(0xffffffffu, mx0, 2));
        mx1 = fmaxf(mx1, __shfl_xor_sync(0xffffffffu, mx1, 1));
        mx1 = fmaxf(mx1, __shfl_xor_sync(0xffffffffu, mx1, 2));

        float m0n = fmaxf(m2_0, mx0);
        float m1n = fmaxf(m2_1, mx1);
        float cor0 = exp2f(m2_0 - m0n);
        float cor1 = exp2f(m2_1 - m1n);
        m2_0 = m0n; m2_1 = m1n;

        uint32_t ph[8][2], pl[8][2];
        float ls0 = 0.f, ls1 = 0.f;
#pragma unroll
        for (int nf = 0; nf < 8; nf++) {
            float p0 = exp2f(sv[nf][0] - m0n);
            float p1 = exp2f(sv[nf][1] - m0n);
            float p2 = exp2f(sv[nf][2] - m1n);
            float p3 = exp2f(sv[nf][3] - m1n);
            ls0 += p0 + p1; ls1 += p2 + p3;
            split2h(p0, p1, ph[nf][0], pl[nf][0]);
            split2h(p2, p3, ph[nf][1], pl[nf][1]);
        }
        ls0 += __shfl_xor_sync(0xffffffffu, ls0, 1);
        ls0 += __shfl_xor_sync(0xffffffffu, ls0, 2);
        ls1 += __shfl_xor_sync(0xffffffffu, ls1, 1);
        ls1 += __shfl_xor_sync(0xffffffffu, ls1, 2);
        l0 = l0 * cor0 + ls0;
        l1 = l1 * cor1 + ls1;

#pragma unroll
        for (int nf = 0; nf < 16; nf++) {
            O[nf][0] *= cor0; O[nf][1] *= cor0;
            O[nf][2] *= cor1; O[nf][3] *= cor1;
        }

#pragma unroll
        for (int kk = 0; kk < 4; kk++) {
            uint32_t aH[4] = {ph[2*kk][0], ph[2*kk][1], ph[2*kk+1][0], ph[2*kk+1][1]};
            uint32_t aL[4] = {pl[2*kk][0], pl[2*kk][1], pl[2*kk+1][0], pl[2*kk+1][1]};
#pragma unroll
            for (int dg = 0; dg < 8; dg++) {
                uint32_t vaddr = sV + kv_row
                               + (uint32_t)(kk * 16 * AST + dg * 16) * 2;
                uint32_t vV[4];
                ldmx4t(vV, vaddr);
                mma_fp16(O[dg * 2],     aH, vV[0], vV[1]);
                mma_fp16(O[dg * 2],     aL, vV[0], vV[1]);
                mma_fp16(O[dg * 2 + 1], aH, vV[2], vV[3]);
                mma_fp16(O[dg * 2 + 1], aL, vV[2], vV[3]);
            }
        }

        __syncthreads();
        if (i + 2 < cnt) { load_kv(list[i + 2], s); CP_COMMIT(); }
        if (i + 1 < cnt) {
            if (i + 2 < cnt) { CP_WAIT(1); } else { CP_WAIT(0); }
            __syncthreads();
        }
    }

    float inv0 = 1.f / l0, inv1 = 1.f / l1;
    int r0 = qrow0 + warp * 16 + (lane >> 2);
    int r1 = r0 + 8;
#pragma unroll
    for (int nf = 0; nf < 16; nf++) {
        int col = part * 128 + nf * 8 + (lane & 3) * 2;
        uint32_t wh, wl;
        split2h(O[nf][0] * inv0, O[nf][1] * inv0, wh, wl);
        *(uint32_t*)(g_Ath + (size_t)r0 * 256 + col) = wh;
        *(uint32_t*)(g_Atl + (size_t)r0 * 256 + col) = wl;
        split2h(O[nf][2] * inv1, O[nf][3] * inv1, wh, wl);
        *(uint32_t*)(g_Ath + (size_t)r1 * 256 + col) = wh;
        *(uint32_t*)(g_Atl + (size_t)r1 * 256 + col) = wl;
    }
}

// ---------------------------------------------------------------------------
// Launch
// ---------------------------------------------------------------------------
extern "C" void kernel_launch(void* const* d_in, const int* in_sizes, int n_in,
                              void* d_out, int out_size)
{
    const float* xin[6];
    for (int i = 0; i < 6; i++) xin[i] = (const float*)d_in[i];
    const float* W_qkv  = (const float*)d_in[6];
    const float* b_qkv  = (const float*)d_in[7];
    const float* W_out  = (const float*)d_in[8];
    const float* b_out  = (const float*)d_in[9];
    const void*  mask   = d_in[10];
    float* out = (float*)d_out;
    (void)in_sizes; (void)n_in; (void)out_size;

    cudaFuncSetAttribute(attn_mma, cudaFuncAttributeMaxDynamicSharedMemorySize,
                         ATT_SMEM);
    cudaFuncSetAttribute(gemm_qkv, cudaFuncAttributeMaxDynamicSharedMemorySize,
                         GEMM_SMEM);
    cudaFuncSetAttribute(gemm_out, cudaFuncAttributeMaxDynamicSharedMemorySize,
                         GEMM_SMEM);

    __half *Wq, *Ath, *Atl, *Wo;
    cudaGetSymbolAddress((void**)&Wq,  g_Wq);
    cudaGetSymbolAddress((void**)&Ath, g_Ath);
    cudaGetSymbolAddress((void**)&Atl, g_Atl);
    cudaGetSymbolAddress((void**)&Wo,  g_Wo);

    build_mask_kernel<<<1, NBQ>>>(mask);                                  // 0
    cvt_kernel<<<(768 * 768 / 4 + 255) / 256, 256>>>((const float4*)W_qkv,
        (uint2*)Wq, 768 * 768 / 4);                                       // 1
    cvt_kernel<<<(256 * 256 / 4 + 255) / 256, 256>>>((const float4*)W_out,
        (uint2*)Wo, 256 * 256 / 4);                                       // 2
    gemm_qkv<<<dim3(3, MTOT / 128), 256, GEMM_SMEM>>>(                    // 3
        xin[0], xin[1], xin[2], xin[3], xin[4], xin[5], Wq, b_qkv);
    attn_mma<<<dim3(NBQ, 2, BQ), 128, ATT_SMEM>>>();                      // 4
    gemm_out<<<dim3(1, MTOT / 128), 256, GEMM_SMEM>>>(                    // 5 <- ncu
        Ath, Atl, Wo, b_out, out);
}